// round 6
// baseline (speedup 1.0000x reference)
#include <cuda_runtime.h>
#include <cuda_bf16.h>
#include <cuda_fp16.h>
#include <float.h>
#include <stdint.h>

typedef __nv_bfloat16 bf16;
typedef __half fp16;

#define T_SEQ   4096
#define DIM     768
#define HEADS   12
#define HEAD_D  64
#define N_QKV   (3 * DIM)
#define RMS_EPS 1.1920928955078125e-07f
#define ATTN_SCALE 0.12f

// ---------------- scratch ----------------------------------------------------
__device__ float g_qkv[3 * HEADS * T_SEQ * HEAD_D];   // f32, head-major
__device__ fp16  g_qh[HEADS * T_SEQ * HEAD_D];        // q hi/lo fp16 (×0.12)
__device__ fp16  g_ql[HEADS * T_SEQ * HEAD_D];
__device__ fp16  g_k [HEADS * T_SEQ * HEAD_D];        // k single fp16
__device__ fp16  g_v [HEADS * T_SEQ * HEAD_D];        // v single fp16
__device__ bf16  g_xh[T_SEQ * DIM],  g_xl[T_SEQ * DIM];
__device__ bf16  g_wqh[N_QKV * DIM], g_wql[N_QKV * DIM];
__device__ bf16  g_wph[DIM * DIM],   g_wpl[DIM * DIM];
__device__ bf16  g_yh[T_SEQ * DIM],  g_yl[T_SEQ * DIM];

// ---------------- helpers ----------------------------------------------------
__device__ __forceinline__ uint32_t smem_u32(const void* p) {
    return (uint32_t)__cvta_generic_to_shared(p);
}
__device__ __forceinline__ void ldsm_x4(uint32_t& r0, uint32_t& r1,
                                        uint32_t& r2, uint32_t& r3, uint32_t a) {
    asm volatile("ldmatrix.sync.aligned.m8n8.x4.shared.b16 {%0,%1,%2,%3},[%4];\n"
                 : "=r"(r0), "=r"(r1), "=r"(r2), "=r"(r3) : "r"(a));
}
__device__ __forceinline__ void ldsm_x4_t(uint32_t& r0, uint32_t& r1,
                                          uint32_t& r2, uint32_t& r3, uint32_t a) {
    asm volatile("ldmatrix.sync.aligned.m8n8.x4.trans.shared.b16 {%0,%1,%2,%3},[%4];\n"
                 : "=r"(r0), "=r"(r1), "=r"(r2), "=r"(r3) : "r"(a));
}
__device__ __forceinline__ void mma_bf(float* d, const uint32_t* a, const uint32_t* b) {
    asm volatile(
        "mma.sync.aligned.m16n8k16.row.col.f32.bf16.bf16.f32 "
        "{%0,%1,%2,%3},{%4,%5,%6,%7},{%8,%9},{%0,%1,%2,%3};\n"
        : "+f"(d[0]), "+f"(d[1]), "+f"(d[2]), "+f"(d[3])
        : "r"(a[0]), "r"(a[1]), "r"(a[2]), "r"(a[3]), "r"(b[0]), "r"(b[1]));
}
__device__ __forceinline__ void mma_fp(float* d, const uint32_t* a, const uint32_t* b) {
    asm volatile(
        "mma.sync.aligned.m16n8k16.row.col.f32.f16.f16.f32 "
        "{%0,%1,%2,%3},{%4,%5,%6,%7},{%8,%9},{%0,%1,%2,%3};\n"
        : "+f"(d[0]), "+f"(d[1]), "+f"(d[2]), "+f"(d[3])
        : "r"(a[0]), "r"(a[1]), "r"(a[2]), "r"(a[3]), "r"(b[0]), "r"(b[1]));
}
__device__ __forceinline__ uint32_t pack_bf2(float x, float y) {
    __nv_bfloat162 t = __floats2bfloat162_rn(x, y);
    return *(uint32_t*)&t;
}
__device__ __forceinline__ uint32_t pack_h2(float x, float y) {
    __half2 t = __floats2half2_rn(x, y);
    return *(uint32_t*)&t;
}
__device__ __forceinline__ void split_bf(float v, bf16& h, bf16& l) {
    h = __float2bfloat16(v);
    l = __float2bfloat16(v - __bfloat162float(h));
}
__device__ __forceinline__ void split_hf(float v, fp16& h, fp16& l) {
    h = __float2half_rn(v);
    l = __float2half_rn(v - __half2float(h));
}

__global__ void split_kernel(const float* __restrict__ in,
                             bf16* __restrict__ hi, bf16* __restrict__ lo, int n) {
    int i = blockIdx.x * blockDim.x + threadIdx.x;
    if (i < n) { bf16 h, l; split_bf(in[i], h, l); hi[i] = h; lo[i] = l; }
}

// ---------------- GEMM: C = A @ B^T, 3-term bf16, 128x128 block --------------
// 256 thr, 8 warps: wm = wid&3 (4 x 32 rows), wn = wid>>2 (2 x 64 cols).
// Warp tile 32x64. BK = 32.
#define LDA 40
template<int MODE>   // 0: scatter into g_qkv ; 1: plain write to C
__global__ __launch_bounds__(256) void gemm_mma_kernel(
    const bf16* __restrict__ Ah, const bf16* __restrict__ Al,
    const bf16* __restrict__ Bh, const bf16* __restrict__ Bl,
    float* __restrict__ C)
{
    constexpr int K = 768;
    __shared__ bf16 sA[2][128][LDA];
    __shared__ bf16 sB[2][128][LDA];
    const int tid = threadIdx.x;
    const int wid = tid >> 5, lane = tid & 31;
    const int wm = wid & 3, wn = wid >> 2;
    const int m0 = blockIdx.x * 128, n0 = blockIdx.y * 128;
    const int g = lane >> 2, q = lane & 3;

    float acc[2][8][4];
    #pragma unroll
    for (int a = 0; a < 2; a++)
        #pragma unroll
        for (int b = 0; b < 8; b++)
            #pragma unroll
            for (int c = 0; c < 4; c++) acc[a][b][c] = 0.f;

    for (int k0 = 0; k0 < K; k0 += 32) {
        __syncthreads();
        #pragma unroll
        for (int i = 0; i < 2; i++) {
            int c = tid + i * 256;               // 0..511
            int r = c >> 2, col = (c & 3) * 8;
            size_t ga = (size_t)(m0 + r) * K + k0 + col;
            size_t gb = (size_t)(n0 + r) * K + k0 + col;
            *(uint4*)&sA[0][r][col] = *(const uint4*)(Ah + ga);
            *(uint4*)&sA[1][r][col] = *(const uint4*)(Al + ga);
            *(uint4*)&sB[0][r][col] = *(const uint4*)(Bh + gb);
            *(uint4*)&sB[1][r][col] = *(const uint4*)(Bl + gb);
        }
        __syncthreads();

        uint32_t aF[2][2][2][4];   // [hi/lo][mt][kt][4]
        uint32_t bF[2][8][2][2];   // [hi/lo][nt][kt][2]
        #pragma unroll
        for (int v = 0; v < 2; v++) {
            #pragma unroll
            for (int mt = 0; mt < 2; mt++)
                #pragma unroll
                for (int kt = 0; kt < 2; kt++) {
                    uint32_t ad = smem_u32(&sA[v][wm * 32 + mt * 16 + (lane & 15)]
                                              [kt * 16 + (lane >> 4) * 8]);
                    ldsm_x4(aF[v][mt][kt][0], aF[v][mt][kt][1],
                            aF[v][mt][kt][2], aF[v][mt][kt][3], ad);
                }
            #pragma unroll
            for (int np = 0; np < 4; np++)
                #pragma unroll
                for (int kt = 0; kt < 2; kt++) {
                    uint32_t ad = smem_u32(&sB[v][wn * 64 + np * 16 + (lane & 15)]
                                              [kt * 16 + (lane >> 4) * 8]);
                    uint32_t r0, r1, r2, r3;
                    ldsm_x4(r0, r1, r2, r3, ad);
                    bF[v][np * 2 + 0][kt][0] = r0; bF[v][np * 2 + 1][kt][0] = r1;
                    bF[v][np * 2 + 0][kt][1] = r2; bF[v][np * 2 + 1][kt][1] = r3;
                }
        }
        #pragma unroll
        for (int mt = 0; mt < 2; mt++)
            #pragma unroll
            for (int nt = 0; nt < 8; nt++)
                #pragma unroll
                for (int kt = 0; kt < 2; kt++) {
                    mma_bf(acc[mt][nt], aF[0][mt][kt], bF[0][nt][kt]);
                    mma_bf(acc[mt][nt], aF[0][mt][kt], bF[1][nt][kt]);
                    mma_bf(acc[mt][nt], aF[1][mt][kt], bF[0][nt][kt]);
                }
    }

    #pragma unroll
    for (int mt = 0; mt < 2; mt++)
        #pragma unroll
        for (int nt = 0; nt < 8; nt++) {
            int r0 = m0 + wm * 32 + mt * 16 + g;
            int cc = n0 + wn * 64 + nt * 8 + q * 2;
            float* a = acc[mt][nt];
            if (MODE == 0) {
                size_t base = (size_t)(cc >> 6) * (T_SEQ * HEAD_D) + (cc & 63);
                *(float2*)&g_qkv[base + (size_t)r0 * HEAD_D]       = make_float2(a[0], a[1]);
                *(float2*)&g_qkv[base + (size_t)(r0 + 8) * HEAD_D] = make_float2(a[2], a[3]);
            } else {
                *(float2*)&C[(size_t)r0 * DIM + cc]       = make_float2(a[0], a[1]);
                *(float2*)&C[(size_t)(r0 + 8) * DIM + cc] = make_float2(a[2], a[3]);
            }
        }
}

// ---------------- RMSNorm + rotary + fp16 outputs ----------------------------
// grid (T, 3): comp 0 -> g_qh/g_ql (×0.12), 1 -> g_k, 2 -> g_v
__global__ void rms_rope_split_kernel() {
    const int t = blockIdx.x;
    const int comp = blockIdx.y;
    const int h = threadIdx.x >> 5;
    const int lane = threadIdx.x & 31;
    const size_t hoff = (size_t)h * (T_SEQ * HEAD_D) + (size_t)t * HEAD_D;
    const float* p = g_qkv + (size_t)comp * HEADS * T_SEQ * HEAD_D + hoff;
    float v0 = p[lane], v1 = p[lane + 32];

    if (comp < 2) {
        float ss = v0 * v0 + v1 * v1;
        #pragma unroll
        for (int o = 16; o >= 1; o >>= 1) ss += __shfl_xor_sync(0xffffffffu, ss, o);
        float r = rsqrtf(ss * (1.0f / HEAD_D) + RMS_EPS);
        v0 *= r; v1 *= r;
        if (lane < 16) {
            float fr = exp2f(-10.0f * (float)lane / 15.0f);
            float th = (float)t * fr, s, c;
            sincosf(th, &s, &c);
            float y0 =  v0 * c + v1 * s;
            float y1 = -v0 * s + v1 * c;
            v0 = y0; v1 = y1;
        }
        if (comp == 0) {
            v0 *= ATTN_SCALE; v1 *= ATTN_SCALE;
            fp16 h0, l0, h1, l1;
            split_hf(v0, h0, l0);
            split_hf(v1, h1, l1);
            g_qh[hoff + lane] = h0;      g_ql[hoff + lane] = l0;
            g_qh[hoff + lane + 32] = h1; g_ql[hoff + lane + 32] = l1;
        } else {
            g_k[hoff + lane]      = __float2half_rn(v0);
            g_k[hoff + lane + 32] = __float2half_rn(v1);
        }
    } else {
        g_v[hoff + lane]      = __float2half_rn(v0);
        g_v[hoff + lane + 32] = __float2half_rn(v1);
    }
}

// ---------------- Flash attention: fp16, QK 2-term, PV 2-term, no-max --------
// |S| <= 0.12*8*8 = 7.68 -> exp always safe; no running max needed.
#define FLD 72
__global__ __launch_bounds__(128) void flash_kernel() {
    __shared__ fp16 sK[64][FLD];
    __shared__ fp16 sV[64][FLD];
    const int qb = (gridDim.x - 1) - blockIdx.x;   // heavy first
    const int h = blockIdx.y;
    const int tid = threadIdx.x, wid = tid >> 5, lane = tid & 31;
    const int g = lane >> 2, q = lane & 3;

    const size_t HS = (size_t)T_SEQ * HEAD_D;
    const fp16* Qh = g_qh + (size_t)h * HS;
    const fp16* Ql = g_ql + (size_t)h * HS;
    const fp16* Kk = g_k  + (size_t)h * HS;
    const fp16* Vv = g_v  + (size_t)h * HS;

    // Q fragments (hi/lo) straight from global
    uint32_t qF[2][4][4];
    {
        int r0 = qb * 64 + wid * 16 + g;
        #pragma unroll
        for (int v = 0; v < 2; v++) {
            const fp16* Qp = v ? Ql : Qh;
            #pragma unroll
            for (int kt = 0; kt < 4; kt++) {
                int c = kt * 16 + q * 2;
                qF[v][kt][0] = *(const uint32_t*)(Qp + (size_t)r0 * HEAD_D + c);
                qF[v][kt][1] = *(const uint32_t*)(Qp + (size_t)(r0 + 8) * HEAD_D + c);
                qF[v][kt][2] = *(const uint32_t*)(Qp + (size_t)r0 * HEAD_D + c + 8);
                qF[v][kt][3] = *(const uint32_t*)(Qp + (size_t)(r0 + 8) * HEAD_D + c + 8);
            }
        }
    }

    float o[8][4];
    #pragma unroll
    for (int i = 0; i < 8; i++)
        #pragma unroll
        for (int j = 0; j < 4; j++) o[i][j] = 0.f;
    float l0_ = 0.f, l1_ = 0.f;

    for (int kb = 0; kb <= qb; kb++) {
        __syncthreads();
        #pragma unroll
        for (int i = 0; i < 4; i++) {
            int c = tid + i * 128;
            int r = c >> 3, col = (c & 7) * 8;
            size_t go = (size_t)(kb * 64 + r) * HEAD_D + col;
            *(uint4*)&sK[r][col] = *(const uint4*)(Kk + go);
            *(uint4*)&sV[r][col] = *(const uint4*)(Vv + go);
        }
        __syncthreads();

        // ---- S = (qh + ql) K^T : 2 fp16 mma per fragment ----
        float s[8][4];
        #pragma unroll
        for (int i = 0; i < 8; i++)
            #pragma unroll
            for (int j = 0; j < 4; j++) s[i][j] = 0.f;

        #pragma unroll
        for (int kt = 0; kt < 4; kt++) {
            uint32_t bh[8][2];
            #pragma unroll
            for (int np = 0; np < 4; np++) {
                uint32_t ad = smem_u32(&sK[np * 16 + (lane & 15)]
                                          [kt * 16 + (lane >> 4) * 8]);
                uint32_t r0, r1, r2, r3;
                ldsm_x4(r0, r1, r2, r3, ad);
                bh[np * 2][0] = r0; bh[np * 2 + 1][0] = r1;
                bh[np * 2][1] = r2; bh[np * 2 + 1][1] = r3;
            }
            #pragma unroll
            for (int nt = 0; nt < 8; nt++) {
                mma_fp(s[nt], qF[0][kt], bh[nt]);
                mma_fp(s[nt], qF[1][kt], bh[nt]);
            }
        }

        // ---- causal mask on diagonal tile ----
        if (kb == qb) {
            int rl0 = wid * 16 + g, rl1 = rl0 + 8;
            #pragma unroll
            for (int nt = 0; nt < 8; nt++) {
                int c0 = nt * 8 + q * 2, c1 = c0 + 1;
                if (c0 > rl0) s[nt][0] = -1e30f;
                if (c1 > rl0) s[nt][1] = -1e30f;
                if (c0 > rl1) s[nt][2] = -1e30f;
                if (c1 > rl1) s[nt][3] = -1e30f;
            }
        }

        // ---- exp + row sums (no max) ----
        float rs0 = 0.f, rs1 = 0.f;
        #pragma unroll
        for (int nt = 0; nt < 8; nt++) {
            s[nt][0] = __expf(s[nt][0]);
            s[nt][1] = __expf(s[nt][1]);
            s[nt][2] = __expf(s[nt][2]);
            s[nt][3] = __expf(s[nt][3]);
            rs0 += s[nt][0] + s[nt][1];
            rs1 += s[nt][2] + s[nt][3];
        }
        rs0 += __shfl_xor_sync(0xffffffffu, rs0, 1);
        rs0 += __shfl_xor_sync(0xffffffffu, rs0, 2);
        rs1 += __shfl_xor_sync(0xffffffffu, rs1, 1);
        rs1 += __shfl_xor_sync(0xffffffffu, rs1, 2);
        l0_ += rs0;
        l1_ += rs1;

        // ---- P -> fp16 hi/lo fragments ----
        uint32_t pF[2][4][4];
        #pragma unroll
        for (int kt = 0; kt < 4; kt++) {
            #pragma unroll
            for (int half = 0; half < 2; half++) {
                float p0 = s[2 * kt + half][0], p1 = s[2 * kt + half][1];
                float p2 = s[2 * kt + half][2], p3 = s[2 * kt + half][3];
                float h0 = __half2float(__float2half_rn(p0));
                float h1 = __half2float(__float2half_rn(p1));
                float h2 = __half2float(__float2half_rn(p2));
                float h3 = __half2float(__float2half_rn(p3));
                pF[0][kt][0 + 2 * half] = pack_h2(h0, h1);
                pF[0][kt][1 + 2 * half] = pack_h2(h2, h3);
                pF[1][kt][0 + 2 * half] = pack_h2(p0 - h0, p1 - h1);
                pF[1][kt][1 + 2 * half] = pack_h2(p2 - h2, p3 - h3);
            }
        }

        // ---- O += (Ph + Pl) V : 2 fp16 mma per fragment ----
        #pragma unroll
        for (int kt = 0; kt < 4; kt++) {
            uint32_t bv[8][2];
            #pragma unroll
            for (int np = 0; np < 4; np++) {
                uint32_t ad = smem_u32(&sV[kt * 16 + (lane & 15)]
                                          [np * 16 + (lane >> 4) * 8]);
                uint32_t r0, r1, r2, r3;
                ldsm_x4_t(r0, r1, r2, r3, ad);
                bv[np * 2][0] = r0; bv[np * 2][1] = r1;
                bv[np * 2 + 1][0] = r2; bv[np * 2 + 1][1] = r3;
            }
            #pragma unroll
            for (int nt = 0; nt < 8; nt++) {
                mma_fp(o[nt], pF[0][kt], bv[nt]);
                mma_fp(o[nt], pF[1][kt], bv[nt]);
            }
        }
    }

    // ---- epilogue: y = O/l, split bf16 hi/lo for proj ----
    float i0 = 1.f / l0_, i1 = 1.f / l1_;
    int t0 = qb * 64 + wid * 16 + g;
    #pragma unroll
    for (int nt = 0; nt < 8; nt++) {
        int d = h * HEAD_D + nt * 8 + q * 2;
        float y0 = o[nt][0] * i0, y1 = o[nt][1] * i0;
        float y2 = o[nt][2] * i1, y3 = o[nt][3] * i1;
        float h0 = __bfloat162float(__float2bfloat16(y0));
        float h1 = __bfloat162float(__float2bfloat16(y1));
        float h2 = __bfloat162float(__float2bfloat16(y2));
        float h3 = __bfloat162float(__float2bfloat16(y3));
        *(uint32_t*)&g_yh[(size_t)t0 * DIM + d]       = pack_bf2(h0, h1);
        *(uint32_t*)&g_yh[(size_t)(t0 + 8) * DIM + d] = pack_bf2(h2, h3);
        *(uint32_t*)&g_yl[(size_t)t0 * DIM + d]       = pack_bf2(y0 - h0, y1 - h1);
        *(uint32_t*)&g_yl[(size_t)(t0 + 8) * DIM + d] = pack_bf2(y2 - h2, y3 - h3);
    }
}

// ---------------------------------------------------------------------------
extern "C" void kernel_launch(void* const* d_in, const int* in_sizes, int n_in,
                              void* d_out, int out_size)
{
    const float* x        = (const float*)d_in[0];
    const float* qkv_w    = (const float*)d_in[1];
    const float* c_proj_w = (const float*)d_in[2];
    float* out            = (float*)d_out;

    bf16 *xh, *xl, *wqh, *wql, *wph, *wpl, *yh, *yl;
    cudaGetSymbolAddress((void**)&xh,  g_xh);  cudaGetSymbolAddress((void**)&xl,  g_xl);
    cudaGetSymbolAddress((void**)&wqh, g_wqh); cudaGetSymbolAddress((void**)&wql, g_wql);
    cudaGetSymbolAddress((void**)&wph, g_wph); cudaGetSymbolAddress((void**)&wpl, g_wpl);
    cudaGetSymbolAddress((void**)&yh,  g_yh);  cudaGetSymbolAddress((void**)&yl,  g_yl);

    {
        int n1 = T_SEQ * DIM, n2 = N_QKV * DIM, n3 = DIM * DIM;
        split_kernel<<<(n1 + 255) / 256, 256>>>(x, xh, xl, n1);
        split_kernel<<<(n2 + 255) / 256, 256>>>(qkv_w, wqh, wql, n2);
        split_kernel<<<(n3 + 255) / 256, 256>>>(c_proj_w, wph, wpl, n3);
    }

    // 1) QKV projection (3-term bf16, 128x128 tiles) -> g_qkv f32 head-major
    gemm_mma_kernel<0><<<dim3(T_SEQ / 128, N_QKV / 128), 256>>>(
        xh, xl, wqh, wql, nullptr);

    // 2) rms + rope -> q hi/lo fp16 (scaled), k fp16, v fp16
    rms_rope_split_kernel<<<dim3(T_SEQ, 3), HEADS * 32>>>();

    // 3) flash attention (fp16 2+2-term, no-max softmax)
    flash_kernel<<<dim3(T_SEQ / 64, HEADS), 128>>>();

    // 4) output projection (3-term bf16, 128x128 tiles) -> out
    gemm_mma_kernel<1><<<dim3(T_SEQ / 128, DIM / 128), 256>>>(yh, yl, wph, wpl, out);
}

// round 7
// speedup vs baseline: 1.2485x; 1.2485x over previous
#include <cuda_runtime.h>
#include <cuda_fp16.h>
#include <float.h>
#include <stdint.h>

typedef __half fp16;

#define T_SEQ   4096
#define DIM     768
#define HEADS   12
#define HEAD_D  64
#define N_QKV   (3 * DIM)
#define RMS_EPS 1.1920928955078125e-07f
#define ATTN_SCALE 0.12f

// ---------------- scratch ----------------------------------------------------
__device__ float g_qkv[3 * HEADS * T_SEQ * HEAD_D];   // f32, head-major
__device__ fp16  g_q [HEADS * T_SEQ * HEAD_D];        // q fp16 (×0.12)
__device__ fp16  g_k [HEADS * T_SEQ * HEAD_D];        // k fp16
__device__ fp16  g_v [HEADS * T_SEQ * HEAD_D];        // v fp16
__device__ fp16  g_xh[T_SEQ * DIM], g_xl[T_SEQ * DIM];
__device__ fp16  g_wq[N_QKV * DIM];                   // single fp16 weights
__device__ fp16  g_wp[DIM * DIM];
__device__ fp16  g_yh[T_SEQ * DIM], g_yl[T_SEQ * DIM];

// ---------------- helpers ----------------------------------------------------
__device__ __forceinline__ uint32_t smem_u32(const void* p) {
    return (uint32_t)__cvta_generic_to_shared(p);
}
__device__ __forceinline__ void ldsm_x4(uint32_t& r0, uint32_t& r1,
                                        uint32_t& r2, uint32_t& r3, uint32_t a) {
    asm volatile("ldmatrix.sync.aligned.m8n8.x4.shared.b16 {%0,%1,%2,%3},[%4];\n"
                 : "=r"(r0), "=r"(r1), "=r"(r2), "=r"(r3) : "r"(a));
}
__device__ __forceinline__ void ldsm_x4_t(uint32_t& r0, uint32_t& r1,
                                          uint32_t& r2, uint32_t& r3, uint32_t a) {
    asm volatile("ldmatrix.sync.aligned.m8n8.x4.trans.shared.b16 {%0,%1,%2,%3},[%4];\n"
                 : "=r"(r0), "=r"(r1), "=r"(r2), "=r"(r3) : "r"(a));
}
__device__ __forceinline__ void mma16816(float* d, const uint32_t* a, const uint32_t* b) {
    asm volatile(
        "mma.sync.aligned.m16n8k16.row.col.f32.f16.f16.f32 "
        "{%0,%1,%2,%3},{%4,%5,%6,%7},{%8,%9},{%0,%1,%2,%3};\n"
        : "+f"(d[0]), "+f"(d[1]), "+f"(d[2]), "+f"(d[3])
        : "r"(a[0]), "r"(a[1]), "r"(a[2]), "r"(a[3]), "r"(b[0]), "r"(b[1]));
}
__device__ __forceinline__ uint32_t pack_h2(float x, float y) {
    __half2 t = __floats2half2_rn(x, y);
    return *(uint32_t*)&t;
}
__device__ __forceinline__ void split_f(float v, fp16& h, fp16& l) {
    h = __float2half_rn(v);
    l = __float2half_rn(v - __half2float(h));
}

__global__ void split2_kernel(const float* __restrict__ in,
                              fp16* __restrict__ hi, fp16* __restrict__ lo, int n) {
    int i = blockIdx.x * blockDim.x + threadIdx.x;
    if (i < n) { fp16 h, l; split_f(in[i], h, l); hi[i] = h; lo[i] = l; }
}
__global__ void conv1_kernel(const float* __restrict__ in,
                             fp16* __restrict__ o, int n) {
    int i = blockIdx.x * blockDim.x + threadIdx.x;
    if (i < n) o[i] = __float2half_rn(in[i]);
}

// ---------------- GEMM: C = A @ B^T, 2-term fp16 (A hi/lo, B single) ---------
// Block 128x64, 256 thr, warps 4(m)x2(n), warp tile 32x32, BK=32. (R5 shape)
#define LDA 40
template<int MODE>   // 0: scatter into g_qkv ; 1: plain write to C
__global__ __launch_bounds__(256) void gemm2_kernel(
    const fp16* __restrict__ Ah, const fp16* __restrict__ Al,
    const fp16* __restrict__ B, float* __restrict__ C)
{
    constexpr int K = 768;
    __shared__ fp16 sA[2][128][LDA];
    __shared__ fp16 sB[64][LDA];
    const int tid = threadIdx.x;
    const int wid = tid >> 5, lane = tid & 31;
    const int wm = wid & 3, wn = wid >> 2;
    const int m0 = blockIdx.x * 128, n0 = blockIdx.y * 64;
    const int g = lane >> 2, q = lane & 3;

    float acc[2][4][4];
    #pragma unroll
    for (int a = 0; a < 2; a++)
        #pragma unroll
        for (int b = 0; b < 4; b++)
            #pragma unroll
            for (int c = 0; c < 4; c++) acc[a][b][c] = 0.f;

    for (int k0 = 0; k0 < K; k0 += 32) {
        __syncthreads();
        #pragma unroll
        for (int i = 0; i < 2; i++) {
            int c = tid + i * 256;               // 0..511
            int r = c >> 2, col = (c & 3) * 8;
            size_t go = (size_t)(m0 + r) * K + k0 + col;
            *(uint4*)&sA[0][r][col] = *(const uint4*)(Ah + go);
            *(uint4*)&sA[1][r][col] = *(const uint4*)(Al + go);
        }
        {
            int r = tid >> 2, col = (tid & 3) * 8;
            size_t go = (size_t)(n0 + r) * K + k0 + col;
            *(uint4*)&sB[r][col] = *(const uint4*)(B + go);
        }
        __syncthreads();

        uint32_t aF[2][2][2][4];   // [hi/lo][mt][kt][4]
        uint32_t bF[4][2][2];      // [nt][kt][2]
        #pragma unroll
        for (int v = 0; v < 2; v++)
            #pragma unroll
            for (int mt = 0; mt < 2; mt++)
                #pragma unroll
                for (int kt = 0; kt < 2; kt++) {
                    uint32_t ad = smem_u32(&sA[v][wm * 32 + mt * 16 + (lane & 15)]
                                              [kt * 16 + (lane >> 4) * 8]);
                    ldsm_x4(aF[v][mt][kt][0], aF[v][mt][kt][1],
                            aF[v][mt][kt][2], aF[v][mt][kt][3], ad);
                }
        #pragma unroll
        for (int np = 0; np < 2; np++)
            #pragma unroll
            for (int kt = 0; kt < 2; kt++) {
                uint32_t ad = smem_u32(&sB[wn * 32 + np * 16 + (lane & 15)]
                                          [kt * 16 + (lane >> 4) * 8]);
                uint32_t r0, r1, r2, r3;
                ldsm_x4(r0, r1, r2, r3, ad);
                bF[np * 2 + 0][kt][0] = r0; bF[np * 2 + 1][kt][0] = r1;
                bF[np * 2 + 0][kt][1] = r2; bF[np * 2 + 1][kt][1] = r3;
            }
        #pragma unroll
        for (int mt = 0; mt < 2; mt++)
            #pragma unroll
            for (int nt = 0; nt < 4; nt++)
                #pragma unroll
                for (int kt = 0; kt < 2; kt++) {
                    mma16816(acc[mt][nt], aF[0][mt][kt], bF[nt][kt]);
                    mma16816(acc[mt][nt], aF[1][mt][kt], bF[nt][kt]);
                }
    }

    #pragma unroll
    for (int mt = 0; mt < 2; mt++)
        #pragma unroll
        for (int nt = 0; nt < 4; nt++) {
            int r0 = m0 + wm * 32 + mt * 16 + g;
            int cc = n0 + wn * 32 + nt * 8 + q * 2;
            float* a = acc[mt][nt];
            if (MODE == 0) {
                size_t base = (size_t)(cc >> 6) * (T_SEQ * HEAD_D) + (cc & 63);
                *(float2*)&g_qkv[base + (size_t)r0 * HEAD_D]       = make_float2(a[0], a[1]);
                *(float2*)&g_qkv[base + (size_t)(r0 + 8) * HEAD_D] = make_float2(a[2], a[3]);
            } else {
                *(float2*)&C[(size_t)r0 * DIM + cc]       = make_float2(a[0], a[1]);
                *(float2*)&C[(size_t)(r0 + 8) * DIM + cc] = make_float2(a[2], a[3]);
            }
        }
}

// ---------------- RMSNorm + rotary -> single fp16 q/k/v ----------------------
__global__ void rms_rope_split_kernel() {
    const int t = blockIdx.x;
    const int comp = blockIdx.y;
    const int h = threadIdx.x >> 5;
    const int lane = threadIdx.x & 31;
    const size_t hoff = (size_t)h * (T_SEQ * HEAD_D) + (size_t)t * HEAD_D;
    const float* p = g_qkv + (size_t)comp * HEADS * T_SEQ * HEAD_D + hoff;
    float v0 = p[lane], v1 = p[lane + 32];

    if (comp < 2) {
        float ss = v0 * v0 + v1 * v1;
        #pragma unroll
        for (int o = 16; o >= 1; o >>= 1) ss += __shfl_xor_sync(0xffffffffu, ss, o);
        float r = rsqrtf(ss * (1.0f / HEAD_D) + RMS_EPS);
        v0 *= r; v1 *= r;
        if (lane < 16) {
            float fr = exp2f(-10.0f * (float)lane / 15.0f);
            float th = (float)t * fr, s, c;
            sincosf(th, &s, &c);
            float y0 =  v0 * c + v1 * s;
            float y1 = -v0 * s + v1 * c;
            v0 = y0; v1 = y1;
        }
        if (comp == 0) {
            v0 *= ATTN_SCALE; v1 *= ATTN_SCALE;
            g_q[hoff + lane]      = __float2half_rn(v0);
            g_q[hoff + lane + 32] = __float2half_rn(v1);
        } else {
            g_k[hoff + lane]      = __float2half_rn(v0);
            g_k[hoff + lane + 32] = __float2half_rn(v1);
        }
    } else {
        g_v[hoff + lane]      = __float2half_rn(v0);
        g_v[hoff + lane + 32] = __float2half_rn(v1);
    }
}

// ---------------- Flash: QK 1-term, PV 2-term (P hi/lo), no-max --------------
// |S| <= 0.12*8*8 = 7.68 -> exp always safe; no running max.
#define FLD 72
__global__ __launch_bounds__(128) void flash_kernel() {
    __shared__ fp16 sK[64][FLD];
    __shared__ fp16 sV[64][FLD];
    const int qb = (gridDim.x - 1) - blockIdx.x;   // heavy first
    const int h = blockIdx.y;
    const int tid = threadIdx.x, wid = tid >> 5, lane = tid & 31;
    const int g = lane >> 2, q = lane & 3;

    const size_t HS = (size_t)T_SEQ * HEAD_D;
    const fp16* Q  = g_q + (size_t)h * HS;
    const fp16* Kk = g_k + (size_t)h * HS;
    const fp16* Vv = g_v + (size_t)h * HS;

    // Q fragments from global (row-major, pairs contiguous)
    uint32_t qF[4][4];
    {
        int r0 = qb * 64 + wid * 16 + g;
        #pragma unroll
        for (int kt = 0; kt < 4; kt++) {
            int c = kt * 16 + q * 2;
            qF[kt][0] = *(const uint32_t*)(Q + (size_t)r0 * HEAD_D + c);
            qF[kt][1] = *(const uint32_t*)(Q + (size_t)(r0 + 8) * HEAD_D + c);
            qF[kt][2] = *(const uint32_t*)(Q + (size_t)r0 * HEAD_D + c + 8);
            qF[kt][3] = *(const uint32_t*)(Q + (size_t)(r0 + 8) * HEAD_D + c + 8);
        }
    }

    float o[8][4];
    #pragma unroll
    for (int i = 0; i < 8; i++)
        #pragma unroll
        for (int j = 0; j < 4; j++) o[i][j] = 0.f;
    float l0_ = 0.f, l1_ = 0.f;

    for (int kb = 0; kb <= qb; kb++) {
        __syncthreads();
        #pragma unroll
        for (int i = 0; i < 4; i++) {
            int c = tid + i * 128;
            int r = c >> 3, col = (c & 7) * 8;
            size_t go = (size_t)(kb * 64 + r) * HEAD_D + col;
            *(uint4*)&sK[r][col] = *(const uint4*)(Kk + go);
            *(uint4*)&sV[r][col] = *(const uint4*)(Vv + go);
        }
        __syncthreads();

        // ---- S = Q K^T (single fp16 mma) ----
        float s[8][4];
        #pragma unroll
        for (int i = 0; i < 8; i++)
            #pragma unroll
            for (int j = 0; j < 4; j++) s[i][j] = 0.f;

        #pragma unroll
        for (int kt = 0; kt < 4; kt++) {
            uint32_t bh[8][2];
            #pragma unroll
            for (int np = 0; np < 4; np++) {
                uint32_t ad = smem_u32(&sK[np * 16 + (lane & 15)]
                                          [kt * 16 + (lane >> 4) * 8]);
                uint32_t r0, r1, r2, r3;
                ldsm_x4(r0, r1, r2, r3, ad);
                bh[np * 2][0] = r0; bh[np * 2 + 1][0] = r1;
                bh[np * 2][1] = r2; bh[np * 2 + 1][1] = r3;
            }
            #pragma unroll
            for (int nt = 0; nt < 8; nt++)
                mma16816(s[nt], qF[kt], bh[nt]);
        }

        // ---- causal mask on diagonal tile ----
        if (kb == qb) {
            int rl0 = wid * 16 + g, rl1 = rl0 + 8;
            #pragma unroll
            for (int nt = 0; nt < 8; nt++) {
                int c0 = nt * 8 + q * 2, c1 = c0 + 1;
                if (c0 > rl0) s[nt][0] = -1e30f;
                if (c1 > rl0) s[nt][1] = -1e30f;
                if (c0 > rl1) s[nt][2] = -1e30f;
                if (c1 > rl1) s[nt][3] = -1e30f;
            }
        }

        // ---- exp + row sums (no max) ----
        float rs0 = 0.f, rs1 = 0.f;
        #pragma unroll
        for (int nt = 0; nt < 8; nt++) {
            s[nt][0] = __expf(s[nt][0]);
            s[nt][1] = __expf(s[nt][1]);
            s[nt][2] = __expf(s[nt][2]);
            s[nt][3] = __expf(s[nt][3]);
            rs0 += s[nt][0] + s[nt][1];
            rs1 += s[nt][2] + s[nt][3];
        }
        rs0 += __shfl_xor_sync(0xffffffffu, rs0, 1);
        rs0 += __shfl_xor_sync(0xffffffffu, rs0, 2);
        rs1 += __shfl_xor_sync(0xffffffffu, rs1, 1);
        rs1 += __shfl_xor_sync(0xffffffffu, rs1, 2);
        l0_ += rs0;
        l1_ += rs1;

        // ---- P -> fp16 hi/lo fragments ----
        uint32_t pF[2][4][4];
        #pragma unroll
        for (int kt = 0; kt < 4; kt++) {
            #pragma unroll
            for (int half = 0; half < 2; half++) {
                float p0 = s[2 * kt + half][0], p1 = s[2 * kt + half][1];
                float p2 = s[2 * kt + half][2], p3 = s[2 * kt + half][3];
                float h0 = __half2float(__float2half_rn(p0));
                float h1 = __half2float(__float2half_rn(p1));
                float h2 = __half2float(__float2half_rn(p2));
                float h3 = __half2float(__float2half_rn(p3));
                pF[0][kt][0 + 2 * half] = pack_h2(h0, h1);
                pF[0][kt][1 + 2 * half] = pack_h2(h2, h3);
                pF[1][kt][0 + 2 * half] = pack_h2(p0 - h0, p1 - h1);
                pF[1][kt][1 + 2 * half] = pack_h2(p2 - h2, p3 - h3);
            }
        }

        // ---- O += (Ph + Pl) V : 2 fp16 mma per fragment ----
        #pragma unroll
        for (int kt = 0; kt < 4; kt++) {
            uint32_t bv[8][2];
            #pragma unroll
            for (int np = 0; np < 4; np++) {
                uint32_t ad = smem_u32(&sV[kt * 16 + (lane & 15)]
                                          [np * 16 + (lane >> 4) * 8]);
                uint32_t r0, r1, r2, r3;
                ldsm_x4_t(r0, r1, r2, r3, ad);
                bv[np * 2][0] = r0; bv[np * 2][1] = r1;
                bv[np * 2 + 1][0] = r2; bv[np * 2 + 1][1] = r3;
            }
            #pragma unroll
            for (int nt = 0; nt < 8; nt++) {
                mma16816(o[nt], pF[0][kt], bv[nt]);
                mma16816(o[nt], pF[1][kt], bv[nt]);
            }
        }
    }

    // ---- epilogue: y = O/l, split fp16 hi/lo for proj ----
    float i0 = 1.f / l0_, i1 = 1.f / l1_;
    int t0 = qb * 64 + wid * 16 + g;
    #pragma unroll
    for (int nt = 0; nt < 8; nt++) {
        int d = h * HEAD_D + nt * 8 + q * 2;
        float y0 = o[nt][0] * i0, y1 = o[nt][1] * i0;
        float y2 = o[nt][2] * i1, y3 = o[nt][3] * i1;
        float h0 = __half2float(__float2half_rn(y0));
        float h1 = __half2float(__float2half_rn(y1));
        float h2 = __half2float(__float2half_rn(y2));
        float h3 = __half2float(__float2half_rn(y3));
        *(uint32_t*)&g_yh[(size_t)t0 * DIM + d]       = pack_h2(h0, h1);
        *(uint32_t*)&g_yh[(size_t)(t0 + 8) * DIM + d] = pack_h2(h2, h3);
        *(uint32_t*)&g_yl[(size_t)t0 * DIM + d]       = pack_h2(y0 - h0, y1 - h1);
        *(uint32_t*)&g_yl[(size_t)(t0 + 8) * DIM + d] = pack_h2(y2 - h2, y3 - h3);
    }
}

// ---------------------------------------------------------------------------
extern "C" void kernel_launch(void* const* d_in, const int* in_sizes, int n_in,
                              void* d_out, int out_size)
{
    const float* x        = (const float*)d_in[0];
    const float* qkv_w    = (const float*)d_in[1];
    const float* c_proj_w = (const float*)d_in[2];
    float* out            = (float*)d_out;

    fp16 *xh, *xl, *wq, *wp, *yh, *yl;
    cudaGetSymbolAddress((void**)&xh, g_xh); cudaGetSymbolAddress((void**)&xl, g_xl);
    cudaGetSymbolAddress((void**)&wq, g_wq); cudaGetSymbolAddress((void**)&wp, g_wp);
    cudaGetSymbolAddress((void**)&yh, g_yh); cudaGetSymbolAddress((void**)&yl, g_yl);

    {
        int n1 = T_SEQ * DIM, n2 = N_QKV * DIM, n3 = DIM * DIM;
        split2_kernel<<<(n1 + 255) / 256, 256>>>(x, xh, xl, n1);
        conv1_kernel<<<(n2 + 255) / 256, 256>>>(qkv_w, wq, n2);
        conv1_kernel<<<(n3 + 255) / 256, 256>>>(c_proj_w, wp, n3);
    }

    // 1) QKV projection (2-term fp16) -> g_qkv f32 head-major
    gemm2_kernel<0><<<dim3(T_SEQ / 128, N_QKV / 64), 256>>>(xh, xl, wq, nullptr);

    // 2) rms + rope -> fp16 q (scaled), k, v
    rms_rope_split_kernel<<<dim3(T_SEQ, 3), HEADS * 32>>>();

    // 3) flash attention (QK 1-term, PV 2-term, no-max)
    flash_kernel<<<dim3(T_SEQ / 64, HEADS), 128>>>();

    // 4) output projection (2-term fp16) -> out
    gemm2_kernel<1><<<dim3(T_SEQ / 128, DIM / 64), 256>>>(yh, yl, wp, out);
}

// round 8
// speedup vs baseline: 1.8174x; 1.4557x over previous
#include <cuda_runtime.h>
#include <cuda_bf16.h>
#include <cuda_fp16.h>
#include <float.h>
#include <stdint.h>

typedef __nv_bfloat16 bf16;
typedef __half fp16;

#define T_SEQ   4096
#define DIM     768
#define HEADS   12
#define HEAD_D  64
#define N_QKV   (3 * DIM)
#define RMS_EPS 1.1920928955078125e-07f
// q pre-scale: 0.12 * log2(e)  (softmax computed with exp2)
#define Q_SCALE 0.17312340490667562f

// ---------------- scratch ----------------------------------------------------
__device__ float g_qkv[3 * HEADS * T_SEQ * HEAD_D];   // f32, head-major
__device__ fp16  g_q [HEADS * T_SEQ * HEAD_D];        // q fp16 (×0.12·log2e)
__device__ fp16  g_k [HEADS * T_SEQ * HEAD_D];        // k fp16
__device__ fp16  g_v [HEADS * T_SEQ * HEAD_D];        // v fp16
__device__ bf16  g_xh[T_SEQ * DIM],  g_xl[T_SEQ * DIM];
__device__ bf16  g_wqh[N_QKV * DIM], g_wql[N_QKV * DIM];
__device__ bf16  g_wph[DIM * DIM],   g_wpl[DIM * DIM];
__device__ bf16  g_yh[T_SEQ * DIM],  g_yl[T_SEQ * DIM];

// ---------------- helpers ----------------------------------------------------
__device__ __forceinline__ uint32_t smem_u32(const void* p) {
    return (uint32_t)__cvta_generic_to_shared(p);
}
__device__ __forceinline__ void ldsm_x4(uint32_t& r0, uint32_t& r1,
                                        uint32_t& r2, uint32_t& r3, uint32_t a) {
    asm volatile("ldmatrix.sync.aligned.m8n8.x4.shared.b16 {%0,%1,%2,%3},[%4];\n"
                 : "=r"(r0), "=r"(r1), "=r"(r2), "=r"(r3) : "r"(a));
}
__device__ __forceinline__ void ldsm_x4_t(uint32_t& r0, uint32_t& r1,
                                          uint32_t& r2, uint32_t& r3, uint32_t a) {
    asm volatile("ldmatrix.sync.aligned.m8n8.x4.trans.shared.b16 {%0,%1,%2,%3},[%4];\n"
                 : "=r"(r0), "=r"(r1), "=r"(r2), "=r"(r3) : "r"(a));
}
__device__ __forceinline__ void mma_bf(float* d, const uint32_t* a, const uint32_t* b) {
    asm volatile(
        "mma.sync.aligned.m16n8k16.row.col.f32.bf16.bf16.f32 "
        "{%0,%1,%2,%3},{%4,%5,%6,%7},{%8,%9},{%0,%1,%2,%3};\n"
        : "+f"(d[0]), "+f"(d[1]), "+f"(d[2]), "+f"(d[3])
        : "r"(a[0]), "r"(a[1]), "r"(a[2]), "r"(a[3]), "r"(b[0]), "r"(b[1]));
}
__device__ __forceinline__ void mma_fp(float* d, const uint32_t* a, const uint32_t* b) {
    asm volatile(
        "mma.sync.aligned.m16n8k16.row.col.f32.f16.f16.f32 "
        "{%0,%1,%2,%3},{%4,%5,%6,%7},{%8,%9},{%0,%1,%2,%3};\n"
        : "+f"(d[0]), "+f"(d[1]), "+f"(d[2]), "+f"(d[3])
        : "r"(a[0]), "r"(a[1]), "r"(a[2]), "r"(a[3]), "r"(b[0]), "r"(b[1]));
}
__device__ __forceinline__ uint32_t pack_bf2(float x, float y) {
    __nv_bfloat162 t = __floats2bfloat162_rn(x, y);
    return *(uint32_t*)&t;
}
__device__ __forceinline__ uint32_t pack_h2(float x, float y) {
    __half2 t = __floats2half2_rn(x, y);
    return *(uint32_t*)&t;
}
__device__ __forceinline__ void split_bf(float v, bf16& h, bf16& l) {
    h = __float2bfloat16(v);
    l = __float2bfloat16(v - __bfloat162float(h));
}

__global__ void split_kernel(const float* __restrict__ in,
                             bf16* __restrict__ hi, bf16* __restrict__ lo, int n) {
    int i = blockIdx.x * blockDim.x + threadIdx.x;
    if (i < n) { bf16 h, l; split_bf(in[i], h, l); hi[i] = h; lo[i] = l; }
}

// ---------------- GEMM: C = A @ B^T, 3-term bf16 (R2 shape: 128x64, BK=32) ---
#define LDA 40
template<int MODE>   // 0: scatter into g_qkv ; 1: plain write to C
__global__ __launch_bounds__(256) void gemm_mma_kernel(
    const bf16* __restrict__ Ah, const bf16* __restrict__ Al,
    const bf16* __restrict__ Bh, const bf16* __restrict__ Bl,
    float* __restrict__ C)
{
    constexpr int K = 768;
    __shared__ bf16 sA[2][128][LDA];
    __shared__ bf16 sB[2][64][LDA];
    const int tid = threadIdx.x;
    const int wid = tid >> 5, lane = tid & 31;
    const int wm = wid & 3, wn = wid >> 2;
    const int m0 = blockIdx.x * 128, n0 = blockIdx.y * 64;
    const int g = lane >> 2, q = lane & 3;

    float acc[2][4][4];
    #pragma unroll
    for (int a = 0; a < 2; a++)
        #pragma unroll
        for (int b = 0; b < 4; b++)
            #pragma unroll
            for (int c = 0; c < 4; c++) acc[a][b][c] = 0.f;

    for (int k0 = 0; k0 < K; k0 += 32) {
        __syncthreads();
        #pragma unroll
        for (int i = 0; i < 2; i++) {
            int c = tid + i * 256;               // 0..511
            int r = c >> 2, col = (c & 3) * 8;
            size_t go = (size_t)(m0 + r) * K + k0 + col;
            *(uint4*)&sA[0][r][col] = *(const uint4*)(Ah + go);
            *(uint4*)&sA[1][r][col] = *(const uint4*)(Al + go);
        }
        {
            int r = tid >> 2, col = (tid & 3) * 8;
            size_t go = (size_t)(n0 + r) * K + k0 + col;
            *(uint4*)&sB[0][r][col] = *(const uint4*)(Bh + go);
            *(uint4*)&sB[1][r][col] = *(const uint4*)(Bl + go);
        }
        __syncthreads();

        uint32_t aF[2][2][2][4];   // [hi/lo][mt][kt][4]
        uint32_t bF[2][4][2][2];   // [hi/lo][nt][kt][2]
        #pragma unroll
        for (int v = 0; v < 2; v++) {
            #pragma unroll
            for (int mt = 0; mt < 2; mt++)
                #pragma unroll
                for (int kt = 0; kt < 2; kt++) {
                    uint32_t ad = smem_u32(&sA[v][wm * 32 + mt * 16 + (lane & 15)]
                                              [kt * 16 + (lane >> 4) * 8]);
                    ldsm_x4(aF[v][mt][kt][0], aF[v][mt][kt][1],
                            aF[v][mt][kt][2], aF[v][mt][kt][3], ad);
                }
            #pragma unroll
            for (int np = 0; np < 2; np++)
                #pragma unroll
                for (int kt = 0; kt < 2; kt++) {
                    uint32_t ad = smem_u32(&sB[v][wn * 32 + np * 16 + (lane & 15)]
                                              [kt * 16 + (lane >> 4) * 8]);
                    uint32_t r0, r1, r2, r3;
                    ldsm_x4(r0, r1, r2, r3, ad);
                    bF[v][np * 2 + 0][kt][0] = r0; bF[v][np * 2 + 1][kt][0] = r1;
                    bF[v][np * 2 + 0][kt][1] = r2; bF[v][np * 2 + 1][kt][1] = r3;
                }
        }
        #pragma unroll
        for (int mt = 0; mt < 2; mt++)
            #pragma unroll
            for (int nt = 0; nt < 4; nt++)
                #pragma unroll
                for (int kt = 0; kt < 2; kt++) {
                    mma_bf(acc[mt][nt], aF[0][mt][kt], bF[0][nt][kt]);
                    mma_bf(acc[mt][nt], aF[0][mt][kt], bF[1][nt][kt]);
                    mma_bf(acc[mt][nt], aF[1][mt][kt], bF[0][nt][kt]);
                }
    }

    #pragma unroll
    for (int mt = 0; mt < 2; mt++)
        #pragma unroll
        for (int nt = 0; nt < 4; nt++) {
            int r0 = m0 + wm * 32 + mt * 16 + g;
            int cc = n0 + wn * 32 + nt * 8 + q * 2;
            float* a = acc[mt][nt];
            if (MODE == 0) {
                size_t base = (size_t)(cc >> 6) * (T_SEQ * HEAD_D) + (cc & 63);
                *(float2*)&g_qkv[base + (size_t)r0 * HEAD_D]       = make_float2(a[0], a[1]);
                *(float2*)&g_qkv[base + (size_t)(r0 + 8) * HEAD_D] = make_float2(a[2], a[3]);
            } else {
                *(float2*)&C[(size_t)r0 * DIM + cc]       = make_float2(a[0], a[1]);
                *(float2*)&C[(size_t)(r0 + 8) * DIM + cc] = make_float2(a[2], a[3]);
            }
        }
}

// ---------------- RMSNorm + rotary -> single fp16 q/k/v ----------------------
__global__ void rms_rope_split_kernel() {
    const int t = blockIdx.x;
    const int comp = blockIdx.y;
    const int h = threadIdx.x >> 5;
    const int lane = threadIdx.x & 31;
    const size_t hoff = (size_t)h * (T_SEQ * HEAD_D) + (size_t)t * HEAD_D;
    const float* p = g_qkv + (size_t)comp * HEADS * T_SEQ * HEAD_D + hoff;
    float v0 = p[lane], v1 = p[lane + 32];

    if (comp < 2) {
        float ss = v0 * v0 + v1 * v1;
        #pragma unroll
        for (int o = 16; o >= 1; o >>= 1) ss += __shfl_xor_sync(0xffffffffu, ss, o);
        float r = rsqrtf(ss * (1.0f / HEAD_D) + RMS_EPS);
        v0 *= r; v1 *= r;
        if (lane < 16) {
            float fr = exp2f(-10.0f * (float)lane / 15.0f);
            float th = (float)t * fr, s, c;
            sincosf(th, &s, &c);
            float y0 =  v0 * c + v1 * s;
            float y1 = -v0 * s + v1 * c;
            v0 = y0; v1 = y1;
        }
        if (comp == 0) {
            v0 *= Q_SCALE; v1 *= Q_SCALE;
            g_q[hoff + lane]      = __float2half_rn(v0);
            g_q[hoff + lane + 32] = __float2half_rn(v1);
        } else {
            g_k[hoff + lane]      = __float2half_rn(v0);
            g_k[hoff + lane + 32] = __float2half_rn(v1);
        }
    } else {
        g_v[hoff + lane]      = __float2half_rn(v0);
        g_v[hoff + lane + 32] = __float2half_rn(v1);
    }
}

// ---------------- Flash: fp16, QK 1-term, PV 1-term, exp2, no-max ------------
// |S| <= 0.12*log2e*64 = 11.1 in log2 domain -> exp2 always safe.
#define FLD 72
__global__ __launch_bounds__(128) void flash_kernel() {
    __shared__ fp16 sK[64][FLD];
    __shared__ fp16 sV[64][FLD];
    const int qb = (gridDim.x - 1) - blockIdx.x;   // heavy first
    const int h = blockIdx.y;
    const int tid = threadIdx.x, wid = tid >> 5, lane = tid & 31;
    const int g = lane >> 2, q = lane & 3;

    const size_t HS = (size_t)T_SEQ * HEAD_D;
    const fp16* Q  = g_q + (size_t)h * HS;
    const fp16* Kk = g_k + (size_t)h * HS;
    const fp16* Vv = g_v + (size_t)h * HS;

    uint32_t qF[4][4];
    {
        int r0 = qb * 64 + wid * 16 + g;
        #pragma unroll
        for (int kt = 0; kt < 4; kt++) {
            int c = kt * 16 + q * 2;
            qF[kt][0] = *(const uint32_t*)(Q + (size_t)r0 * HEAD_D + c);
            qF[kt][1] = *(const uint32_t*)(Q + (size_t)(r0 + 8) * HEAD_D + c);
            qF[kt][2] = *(const uint32_t*)(Q + (size_t)r0 * HEAD_D + c + 8);
            qF[kt][3] = *(const uint32_t*)(Q + (size_t)(r0 + 8) * HEAD_D + c + 8);
        }
    }

    float o[8][4];
    #pragma unroll
    for (int i = 0; i < 8; i++)
        #pragma unroll
        for (int j = 0; j < 4; j++) o[i][j] = 0.f;
    float l0_ = 0.f, l1_ = 0.f;

    for (int kb = 0; kb <= qb; kb++) {
        __syncthreads();
        #pragma unroll
        for (int i = 0; i < 4; i++) {
            int c = tid + i * 128;
            int r = c >> 3, col = (c & 7) * 8;
            size_t go = (size_t)(kb * 64 + r) * HEAD_D + col;
            *(uint4*)&sK[r][col] = *(const uint4*)(Kk + go);
            *(uint4*)&sV[r][col] = *(const uint4*)(Vv + go);
        }
        __syncthreads();

        // ---- S = Q K^T (1 fp16 mma per fragment) ----
        float s[8][4];
        #pragma unroll
        for (int i = 0; i < 8; i++)
            #pragma unroll
            for (int j = 0; j < 4; j++) s[i][j] = 0.f;

        #pragma unroll
        for (int kt = 0; kt < 4; kt++) {
            uint32_t bh[8][2];
            #pragma unroll
            for (int np = 0; np < 4; np++) {
                uint32_t ad = smem_u32(&sK[np * 16 + (lane & 15)]
                                          [kt * 16 + (lane >> 4) * 8]);
                uint32_t r0, r1, r2, r3;
                ldsm_x4(r0, r1, r2, r3, ad);
                bh[np * 2][0] = r0; bh[np * 2 + 1][0] = r1;
                bh[np * 2][1] = r2; bh[np * 2 + 1][1] = r3;
            }
            #pragma unroll
            for (int nt = 0; nt < 8; nt++)
                mma_fp(s[nt], qF[kt], bh[nt]);
        }

        // ---- causal mask on diagonal tile ----
        if (kb == qb) {
            int rl0 = wid * 16 + g, rl1 = rl0 + 8;
            #pragma unroll
            for (int nt = 0; nt < 8; nt++) {
                int c0 = nt * 8 + q * 2, c1 = c0 + 1;
                if (c0 > rl0) s[nt][0] = -1e30f;
                if (c1 > rl0) s[nt][1] = -1e30f;
                if (c0 > rl1) s[nt][2] = -1e30f;
                if (c1 > rl1) s[nt][3] = -1e30f;
            }
        }

        // ---- P = exp2(S) + row sums (no max; base folded into q) ----
        float rs0 = 0.f, rs1 = 0.f;
        #pragma unroll
        for (int nt = 0; nt < 8; nt++) {
            s[nt][0] = exp2f(s[nt][0]);
            s[nt][1] = exp2f(s[nt][1]);
            s[nt][2] = exp2f(s[nt][2]);
            s[nt][3] = exp2f(s[nt][3]);
            rs0 += s[nt][0] + s[nt][1];
            rs1 += s[nt][2] + s[nt][3];
        }
        rs0 += __shfl_xor_sync(0xffffffffu, rs0, 1);
        rs0 += __shfl_xor_sync(0xffffffffu, rs0, 2);
        rs1 += __shfl_xor_sync(0xffffffffu, rs1, 1);
        rs1 += __shfl_xor_sync(0xffffffffu, rs1, 2);
        l0_ += rs0;
        l1_ += rs1;

        // ---- P -> single fp16 fragments ----
        uint32_t pF[4][4];
        #pragma unroll
        for (int kt = 0; kt < 4; kt++) {
            #pragma unroll
            for (int half = 0; half < 2; half++) {
                float* sv = s[2 * kt + half];
                pF[kt][0 + 2 * half] = pack_h2(sv[0], sv[1]);
                pF[kt][1 + 2 * half] = pack_h2(sv[2], sv[3]);
            }
        }

        // ---- O += P V (1 fp16 mma per fragment) ----
        #pragma unroll
        for (int kt = 0; kt < 4; kt++) {
            uint32_t bv[8][2];
            #pragma unroll
            for (int np = 0; np < 4; np++) {
                uint32_t ad = smem_u32(&sV[kt * 16 + (lane & 15)]
                                          [np * 16 + (lane >> 4) * 8]);
                uint32_t r0, r1, r2, r3;
                ldsm_x4_t(r0, r1, r2, r3, ad);
                bv[np * 2][0] = r0; bv[np * 2][1] = r1;
                bv[np * 2 + 1][0] = r2; bv[np * 2 + 1][1] = r3;
            }
            #pragma unroll
            for (int nt = 0; nt < 8; nt++)
                mma_fp(o[nt], pF[kt], bv[nt]);
        }
    }

    // ---- epilogue: y = O/l, split bf16 hi/lo for the bf16 proj ----
    float i0 = 1.f / l0_, i1 = 1.f / l1_;
    int t0 = qb * 64 + wid * 16 + g;
    #pragma unroll
    for (int nt = 0; nt < 8; nt++) {
        int d = h * HEAD_D + nt * 8 + q * 2;
        float y0 = o[nt][0] * i0, y1 = o[nt][1] * i0;
        float y2 = o[nt][2] * i1, y3 = o[nt][3] * i1;
        float h0 = __bfloat162float(__float2bfloat16(y0));
        float h1 = __bfloat162float(__float2bfloat16(y1));
        float h2 = __bfloat162float(__float2bfloat16(y2));
        float h3 = __bfloat162float(__float2bfloat16(y3));
        *(uint32_t*)&g_yh[(size_t)t0 * DIM + d]       = pack_bf2(h0, h1);
        *(uint32_t*)&g_yh[(size_t)(t0 + 8) * DIM + d] = pack_bf2(h2, h3);
        *(uint32_t*)&g_yl[(size_t)t0 * DIM + d]       = pack_bf2(y0 - h0, y1 - h1);
        *(uint32_t*)&g_yl[(size_t)(t0 + 8) * DIM + d] = pack_bf2(y2 - h2, y3 - h3);
    }
}

// ---------------------------------------------------------------------------
extern "C" void kernel_launch(void* const* d_in, const int* in_sizes, int n_in,
                              void* d_out, int out_size)
{
    const float* x        = (const float*)d_in[0];
    const float* qkv_w    = (const float*)d_in[1];
    const float* c_proj_w = (const float*)d_in[2];
    float* out            = (float*)d_out;

    bf16 *xh, *xl, *wqh, *wql, *wph, *wpl, *yh, *yl;
    cudaGetSymbolAddress((void**)&xh,  g_xh);  cudaGetSymbolAddress((void**)&xl,  g_xl);
    cudaGetSymbolAddress((void**)&wqh, g_wqh); cudaGetSymbolAddress((void**)&wql, g_wql);
    cudaGetSymbolAddress((void**)&wph, g_wph); cudaGetSymbolAddress((void**)&wpl, g_wpl);
    cudaGetSymbolAddress((void**)&yh,  g_yh);  cudaGetSymbolAddress((void**)&yl,  g_yl);

    {
        int n1 = T_SEQ * DIM, n2 = N_QKV * DIM, n3 = DIM * DIM;
        split_kernel<<<(n1 + 255) / 256, 256>>>(x, xh, xl, n1);
        split_kernel<<<(n2 + 255) / 256, 256>>>(qkv_w, wqh, wql, n2);
        split_kernel<<<(n3 + 255) / 256, 256>>>(c_proj_w, wph, wpl, n3);
    }

    // 1) QKV projection (3-term bf16, R2 shape) -> g_qkv f32 head-major
    gemm_mma_kernel<0><<<dim3(T_SEQ / 128, N_QKV / 64), 256>>>(
        xh, xl, wqh, wql, nullptr);

    // 2) rms + rope -> fp16 q (×0.12·log2e), k, v
    rms_rope_split_kernel<<<dim3(T_SEQ, 3), HEADS * 32>>>();

    // 3) flash attention (fp16 1+1-term, exp2, no-max)
    flash_kernel<<<dim3(T_SEQ / 64, HEADS), 128>>>();

    // 4) output projection (3-term bf16) -> out
    gemm_mma_kernel<1><<<dim3(T_SEQ / 128, DIM / 64), 256>>>(yh, yl, wph, wpl, out);
}

// round 9
// speedup vs baseline: 1.8808x; 1.0349x over previous
#include <cuda_runtime.h>
#include <cuda_bf16.h>
#include <cuda_fp16.h>
#include <float.h>
#include <stdint.h>

typedef __nv_bfloat16 bf16;
typedef __half fp16;

#define T_SEQ   4096
#define DIM     768
#define HEADS   12
#define HEAD_D  64
#define N_QKV   (3 * DIM)
#define RMS_EPS 1.1920928955078125e-07f
// q pre-scale: 0.12 * log2(e)  (softmax computed with exp2)
#define Q_SCALE 0.17312340490667562f

// ---------------- scratch ----------------------------------------------------
__device__ float g_qkv[2 * HEADS * T_SEQ * HEAD_D];   // f32 q,k head-major
__device__ fp16  g_q [HEADS * T_SEQ * HEAD_D];        // q fp16 (×0.12·log2e)
__device__ fp16  g_k [HEADS * T_SEQ * HEAD_D];        // k fp16
__device__ fp16  g_v [HEADS * T_SEQ * HEAD_D];        // v fp16 (direct from GEMM)
__device__ bf16  g_xh[T_SEQ * DIM],  g_xl[T_SEQ * DIM];
__device__ bf16  g_wqh[N_QKV * DIM], g_wql[N_QKV * DIM];
__device__ bf16  g_wph[DIM * DIM],   g_wpl[DIM * DIM];
__device__ bf16  g_yh[T_SEQ * DIM],  g_yl[T_SEQ * DIM];

// ---------------- helpers ----------------------------------------------------
__device__ __forceinline__ uint32_t smem_u32(const void* p) {
    return (uint32_t)__cvta_generic_to_shared(p);
}
__device__ __forceinline__ void ldsm_x4(uint32_t& r0, uint32_t& r1,
                                        uint32_t& r2, uint32_t& r3, uint32_t a) {
    asm volatile("ldmatrix.sync.aligned.m8n8.x4.shared.b16 {%0,%1,%2,%3},[%4];\n"
                 : "=r"(r0), "=r"(r1), "=r"(r2), "=r"(r3) : "r"(a));
}
__device__ __forceinline__ void ldsm_x4_t(uint32_t& r0, uint32_t& r1,
                                          uint32_t& r2, uint32_t& r3, uint32_t a) {
    asm volatile("ldmatrix.sync.aligned.m8n8.x4.trans.shared.b16 {%0,%1,%2,%3},[%4];\n"
                 : "=r"(r0), "=r"(r1), "=r"(r2), "=r"(r3) : "r"(a));
}
__device__ __forceinline__ void mma_bf(float* d, const uint32_t* a, const uint32_t* b) {
    asm volatile(
        "mma.sync.aligned.m16n8k16.row.col.f32.bf16.bf16.f32 "
        "{%0,%1,%2,%3},{%4,%5,%6,%7},{%8,%9},{%0,%1,%2,%3};\n"
        : "+f"(d[0]), "+f"(d[1]), "+f"(d[2]), "+f"(d[3])
        : "r"(a[0]), "r"(a[1]), "r"(a[2]), "r"(a[3]), "r"(b[0]), "r"(b[1]));
}
__device__ __forceinline__ void mma_fp(float* d, const uint32_t* a, const uint32_t* b) {
    asm volatile(
        "mma.sync.aligned.m16n8k16.row.col.f32.f16.f16.f32 "
        "{%0,%1,%2,%3},{%4,%5,%6,%7},{%8,%9},{%0,%1,%2,%3};\n"
        : "+f"(d[0]), "+f"(d[1]), "+f"(d[2]), "+f"(d[3])
        : "r"(a[0]), "r"(a[1]), "r"(a[2]), "r"(a[3]), "r"(b[0]), "r"(b[1]));
}
__device__ __forceinline__ uint32_t pack_bf2(float x, float y) {
    __nv_bfloat162 t = __floats2bfloat162_rn(x, y);
    return *(uint32_t*)&t;
}
__device__ __forceinline__ uint32_t pack_h2(float x, float y) {
    __half2 t = __floats2half2_rn(x, y);
    return *(uint32_t*)&t;
}
__device__ __forceinline__ void split_bf(float v, bf16& h, bf16& l) {
    h = __float2bfloat16(v);
    l = __float2bfloat16(v - __bfloat162float(h));
}

// One kernel splits x, qkv_w, c_proj_w into bf16 hi/lo
#define N_X  (T_SEQ * DIM)
#define N_WQ (N_QKV * DIM)
#define N_WP (DIM * DIM)
__global__ void split_all_kernel(const float* __restrict__ x,
                                 const float* __restrict__ wq,
                                 const float* __restrict__ wp) {
    int i = blockIdx.x * blockDim.x + threadIdx.x;
    const float* in; bf16 *hi, *lo; int idx;
    if (i < N_X)               { in = x;  hi = g_xh;  lo = g_xl;  idx = i; }
    else if (i < N_X + N_WQ)   { in = wq; hi = g_wqh; lo = g_wql; idx = i - N_X; }
    else if (i < N_X + N_WQ + N_WP) { in = wp; hi = g_wph; lo = g_wpl; idx = i - N_X - N_WQ; }
    else return;
    bf16 h, l; split_bf(in[idx], h, l);
    hi[idx] = h; lo[idx] = l;
}

// ---------------- GEMM: C = A @ B^T, 3-term bf16 (128x64 tile, BK=32) --------
// MODE 0: QKV — q,k blocks -> f32 g_qkv head-major; v blocks -> fp16 g_v direct
// MODE 1: proj — plain f32 write to C
#define LDA 40
template<int MODE>
__global__ __launch_bounds__(256) void gemm_mma_kernel(
    const bf16* __restrict__ Ah, const bf16* __restrict__ Al,
    const bf16* __restrict__ Bh, const bf16* __restrict__ Bl,
    float* __restrict__ C)
{
    constexpr int K = 768;
    __shared__ bf16 sA[2][128][LDA];
    __shared__ bf16 sB[2][64][LDA];
    const int tid = threadIdx.x;
    const int wid = tid >> 5, lane = tid & 31;
    const int wm = wid & 3, wn = wid >> 2;
    const int m0 = blockIdx.x * 128, n0 = blockIdx.y * 64;
    const int g = lane >> 2, q = lane & 3;

    float acc[2][4][4];
    #pragma unroll
    for (int a = 0; a < 2; a++)
        #pragma unroll
        for (int b = 0; b < 4; b++)
            #pragma unroll
            for (int c = 0; c < 4; c++) acc[a][b][c] = 0.f;

    for (int k0 = 0; k0 < K; k0 += 32) {
        __syncthreads();
        #pragma unroll
        for (int i = 0; i < 2; i++) {
            int c = tid + i * 256;               // 0..511
            int r = c >> 2, col = (c & 3) * 8;
            size_t go = (size_t)(m0 + r) * K + k0 + col;
            *(uint4*)&sA[0][r][col] = *(const uint4*)(Ah + go);
            *(uint4*)&sA[1][r][col] = *(const uint4*)(Al + go);
        }
        {
            int r = tid >> 2, col = (tid & 3) * 8;
            size_t go = (size_t)(n0 + r) * K + k0 + col;
            *(uint4*)&sB[0][r][col] = *(const uint4*)(Bh + go);
            *(uint4*)&sB[1][r][col] = *(const uint4*)(Bl + go);
        }
        __syncthreads();

        uint32_t aF[2][2][2][4];   // [hi/lo][mt][kt][4]
        uint32_t bF[2][4][2][2];   // [hi/lo][nt][kt][2]
        #pragma unroll
        for (int v = 0; v < 2; v++) {
            #pragma unroll
            for (int mt = 0; mt < 2; mt++)
                #pragma unroll
                for (int kt = 0; kt < 2; kt++) {
                    uint32_t ad = smem_u32(&sA[v][wm * 32 + mt * 16 + (lane & 15)]
                                              [kt * 16 + (lane >> 4) * 8]);
                    ldsm_x4(aF[v][mt][kt][0], aF[v][mt][kt][1],
                            aF[v][mt][kt][2], aF[v][mt][kt][3], ad);
                }
            #pragma unroll
            for (int np = 0; np < 2; np++)
                #pragma unroll
                for (int kt = 0; kt < 2; kt++) {
                    uint32_t ad = smem_u32(&sB[v][wn * 32 + np * 16 + (lane & 15)]
                                              [kt * 16 + (lane >> 4) * 8]);
                    uint32_t r0, r1, r2, r3;
                    ldsm_x4(r0, r1, r2, r3, ad);
                    bF[v][np * 2 + 0][kt][0] = r0; bF[v][np * 2 + 1][kt][0] = r1;
                    bF[v][np * 2 + 0][kt][1] = r2; bF[v][np * 2 + 1][kt][1] = r3;
                }
        }
        #pragma unroll
        for (int mt = 0; mt < 2; mt++)
            #pragma unroll
            for (int nt = 0; nt < 4; nt++)
                #pragma unroll
                for (int kt = 0; kt < 2; kt++) {
                    mma_bf(acc[mt][nt], aF[0][mt][kt], bF[0][nt][kt]);
                    mma_bf(acc[mt][nt], aF[0][mt][kt], bF[1][nt][kt]);
                    mma_bf(acc[mt][nt], aF[1][mt][kt], bF[0][nt][kt]);
                }
    }

    #pragma unroll
    for (int mt = 0; mt < 2; mt++)
        #pragma unroll
        for (int nt = 0; nt < 4; nt++) {
            int r0 = m0 + wm * 32 + mt * 16 + g;
            int cc = n0 + wn * 32 + nt * 8 + q * 2;
            float* a = acc[mt][nt];
            if (MODE == 0) {
                int blk = cc >> 6;                    // 0..35 (comp*12 + head)
                if (blk < 24) {
                    // q or k -> f32 scratch for rms/rope
                    size_t base = (size_t)blk * (T_SEQ * HEAD_D) + (cc & 63);
                    *(float2*)&g_qkv[base + (size_t)r0 * HEAD_D]       = make_float2(a[0], a[1]);
                    *(float2*)&g_qkv[base + (size_t)(r0 + 8) * HEAD_D] = make_float2(a[2], a[3]);
                } else {
                    // v -> fp16 direct (same rounding as old rms pass)
                    size_t base = (size_t)(blk - 24) * (T_SEQ * HEAD_D) + (cc & 63);
                    *(uint32_t*)&g_v[base + (size_t)r0 * HEAD_D]       = pack_h2(a[0], a[1]);
                    *(uint32_t*)&g_v[base + (size_t)(r0 + 8) * HEAD_D] = pack_h2(a[2], a[3]);
                }
            } else {
                *(float2*)&C[(size_t)r0 * DIM + cc]       = make_float2(a[0], a[1]);
                *(float2*)&C[(size_t)(r0 + 8) * DIM + cc] = make_float2(a[2], a[3]);
            }
        }
}

// ---------------- RMSNorm + rotary -> fp16 q (scaled) / k --------------------
__global__ void rms_rope_kernel() {
    const int t = blockIdx.x;
    const int comp = blockIdx.y;                  // 0 = q, 1 = k
    const int h = threadIdx.x >> 5;
    const int lane = threadIdx.x & 31;
    const size_t hoff = (size_t)h * (T_SEQ * HEAD_D) + (size_t)t * HEAD_D;
    const float* p = g_qkv + (size_t)comp * HEADS * T_SEQ * HEAD_D + hoff;
    float v0 = p[lane], v1 = p[lane + 32];

    float ss = v0 * v0 + v1 * v1;
    #pragma unroll
    for (int o = 16; o >= 1; o >>= 1) ss += __shfl_xor_sync(0xffffffffu, ss, o);
    float r = rsqrtf(ss * (1.0f / HEAD_D) + RMS_EPS);
    v0 *= r; v1 *= r;
    if (lane < 16) {
        float fr = exp2f(-10.0f * (float)lane / 15.0f);
        float th = (float)t * fr, s, c;
        sincosf(th, &s, &c);
        float y0 =  v0 * c + v1 * s;
        float y1 = -v0 * s + v1 * c;
        v0 = y0; v1 = y1;
    }
    if (comp == 0) {
        v0 *= Q_SCALE; v1 *= Q_SCALE;
        g_q[hoff + lane]      = __float2half_rn(v0);
        g_q[hoff + lane + 32] = __float2half_rn(v1);
    } else {
        g_k[hoff + lane]      = __float2half_rn(v0);
        g_k[hoff + lane + 32] = __float2half_rn(v1);
    }
}

// ---------------- Flash: fp16, QK 1-term, PV 1-term, exp2, no-max ------------
// |S| <= 0.12*log2e*64 = 11.1 in log2 domain -> exp2 always safe.
#define FLD 72
__global__ __launch_bounds__(128) void flash_kernel() {
    __shared__ fp16 sK[64][FLD];
    __shared__ fp16 sV[64][FLD];
    const int qb = (gridDim.x - 1) - blockIdx.x;   // heavy first
    const int h = blockIdx.y;
    const int tid = threadIdx.x, wid = tid >> 5, lane = tid & 31;
    const int g = lane >> 2, q = lane & 3;

    const size_t HS = (size_t)T_SEQ * HEAD_D;
    const fp16* Q  = g_q + (size_t)h * HS;
    const fp16* Kk = g_k + (size_t)h * HS;
    const fp16* Vv = g_v + (size_t)h * HS;

    uint32_t qF[4][4];
    {
        int r0 = qb * 64 + wid * 16 + g;
        #pragma unroll
        for (int kt = 0; kt < 4; kt++) {
            int c = kt * 16 + q * 2;
            qF[kt][0] = *(const uint32_t*)(Q + (size_t)r0 * HEAD_D + c);
            qF[kt][1] = *(const uint32_t*)(Q + (size_t)(r0 + 8) * HEAD_D + c);
            qF[kt][2] = *(const uint32_t*)(Q + (size_t)r0 * HEAD_D + c + 8);
            qF[kt][3] = *(const uint32_t*)(Q + (size_t)(r0 + 8) * HEAD_D + c + 8);
        }
    }

    float o[8][4];
    #pragma unroll
    for (int i = 0; i < 8; i++)
        #pragma unroll
        for (int j = 0; j < 4; j++) o[i][j] = 0.f;
    float l0_ = 0.f, l1_ = 0.f;

    for (int kb = 0; kb <= qb; kb++) {
        __syncthreads();
        #pragma unroll
        for (int i = 0; i < 4; i++) {
            int c = tid + i * 128;
            int r = c >> 3, col = (c & 7) * 8;
            size_t go = (size_t)(kb * 64 + r) * HEAD_D + col;
            *(uint4*)&sK[r][col] = *(const uint4*)(Kk + go);
            *(uint4*)&sV[r][col] = *(const uint4*)(Vv + go);
        }
        __syncthreads();

        // ---- S = Q K^T ----
        float s[8][4];
        #pragma unroll
        for (int i = 0; i < 8; i++)
            #pragma unroll
            for (int j = 0; j < 4; j++) s[i][j] = 0.f;

        #pragma unroll
        for (int kt = 0; kt < 4; kt++) {
            uint32_t bh[8][2];
            #pragma unroll
            for (int np = 0; np < 4; np++) {
                uint32_t ad = smem_u32(&sK[np * 16 + (lane & 15)]
                                          [kt * 16 + (lane >> 4) * 8]);
                uint32_t r0, r1, r2, r3;
                ldsm_x4(r0, r1, r2, r3, ad);
                bh[np * 2][0] = r0; bh[np * 2 + 1][0] = r1;
                bh[np * 2][1] = r2; bh[np * 2 + 1][1] = r3;
            }
            #pragma unroll
            for (int nt = 0; nt < 8; nt++)
                mma_fp(s[nt], qF[kt], bh[nt]);
        }

        // ---- causal mask on diagonal tile ----
        if (kb == qb) {
            int rl0 = wid * 16 + g, rl1 = rl0 + 8;
            #pragma unroll
            for (int nt = 0; nt < 8; nt++) {
                int c0 = nt * 8 + q * 2, c1 = c0 + 1;
                if (c0 > rl0) s[nt][0] = -1e30f;
                if (c1 > rl0) s[nt][1] = -1e30f;
                if (c0 > rl1) s[nt][2] = -1e30f;
                if (c1 > rl1) s[nt][3] = -1e30f;
            }
        }

        // ---- P = exp2(S) + row sums (no max; base folded into q) ----
        float rs0 = 0.f, rs1 = 0.f;
        #pragma unroll
        for (int nt = 0; nt < 8; nt++) {
            s[nt][0] = exp2f(s[nt][0]);
            s[nt][1] = exp2f(s[nt][1]);
            s[nt][2] = exp2f(s[nt][2]);
            s[nt][3] = exp2f(s[nt][3]);
            rs0 += s[nt][0] + s[nt][1];
            rs1 += s[nt][2] + s[nt][3];
        }
        rs0 += __shfl_xor_sync(0xffffffffu, rs0, 1);
        rs0 += __shfl_xor_sync(0xffffffffu, rs0, 2);
        rs1 += __shfl_xor_sync(0xffffffffu, rs1, 1);
        rs1 += __shfl_xor_sync(0xffffffffu, rs1, 2);
        l0_ += rs0;
        l1_ += rs1;

        // ---- P -> single fp16 fragments ----
        uint32_t pF[4][4];
        #pragma unroll
        for (int kt = 0; kt < 4; kt++) {
            #pragma unroll
            for (int half = 0; half < 2; half++) {
                float* sv = s[2 * kt + half];
                pF[kt][0 + 2 * half] = pack_h2(sv[0], sv[1]);
                pF[kt][1 + 2 * half] = pack_h2(sv[2], sv[3]);
            }
        }

        // ---- O += P V ----
        #pragma unroll
        for (int kt = 0; kt < 4; kt++) {
            uint32_t bv[8][2];
            #pragma unroll
            for (int np = 0; np < 4; np++) {
                uint32_t ad = smem_u32(&sV[kt * 16 + (lane & 15)]
                                          [np * 16 + (lane >> 4) * 8]);
                uint32_t r0, r1, r2, r3;
                ldsm_x4_t(r0, r1, r2, r3, ad);
                bv[np * 2][0] = r0; bv[np * 2][1] = r1;
                bv[np * 2 + 1][0] = r2; bv[np * 2 + 1][1] = r3;
            }
            #pragma unroll
            for (int nt = 0; nt < 8; nt++)
                mma_fp(o[nt], pF[kt], bv[nt]);
        }
    }

    // ---- epilogue: y = O/l, split bf16 hi/lo for the bf16 proj ----
    float i0 = 1.f / l0_, i1 = 1.f / l1_;
    int t0 = qb * 64 + wid * 16 + g;
    #pragma unroll
    for (int nt = 0; nt < 8; nt++) {
        int d = h * HEAD_D + nt * 8 + q * 2;
        float y0 = o[nt][0] * i0, y1 = o[nt][1] * i0;
        float y2 = o[nt][2] * i1, y3 = o[nt][3] * i1;
        float h0 = __bfloat162float(__float2bfloat16(y0));
        float h1 = __bfloat162float(__float2bfloat16(y1));
        float h2 = __bfloat162float(__float2bfloat16(y2));
        float h3 = __bfloat162float(__float2bfloat16(y3));
        *(uint32_t*)&g_yh[(size_t)t0 * DIM + d]       = pack_bf2(h0, h1);
        *(uint32_t*)&g_yh[(size_t)(t0 + 8) * DIM + d] = pack_bf2(h2, h3);
        *(uint32_t*)&g_yl[(size_t)t0 * DIM + d]       = pack_bf2(y0 - h0, y1 - h1);
        *(uint32_t*)&g_yl[(size_t)(t0 + 8) * DIM + d] = pack_bf2(y2 - h2, y3 - h3);
    }
}

// ---------------------------------------------------------------------------
extern "C" void kernel_launch(void* const* d_in, const int* in_sizes, int n_in,
                              void* d_out, int out_size)
{
    const float* x        = (const float*)d_in[0];
    const float* qkv_w    = (const float*)d_in[1];
    const float* c_proj_w = (const float*)d_in[2];
    float* out            = (float*)d_out;

    bf16 *xh, *xl, *wqh, *wql, *wph, *wpl, *yh, *yl;
    cudaGetSymbolAddress((void**)&xh,  g_xh);  cudaGetSymbolAddress((void**)&xl,  g_xl);
    cudaGetSymbolAddress((void**)&wqh, g_wqh); cudaGetSymbolAddress((void**)&wql, g_wql);
    cudaGetSymbolAddress((void**)&wph, g_wph); cudaGetSymbolAddress((void**)&wpl, g_wpl);
    cudaGetSymbolAddress((void**)&yh,  g_yh);  cudaGetSymbolAddress((void**)&yl,  g_yl);

    // 0) one fused split for x, qkv_w, c_proj_w
    {
        int n = N_X + N_WQ + N_WP;
        split_all_kernel<<<(n + 255) / 256, 256>>>(x, qkv_w, c_proj_w);
    }

    // 1) QKV projection (3-term bf16) -> f32 q,k + fp16 v directly
    gemm_mma_kernel<0><<<dim3(T_SEQ / 128, N_QKV / 64), 256>>>(
        xh, xl, wqh, wql, nullptr);

    // 2) rms + rope -> fp16 q (×0.12·log2e), k
    rms_rope_kernel<<<dim3(T_SEQ, 2), HEADS * 32>>>();

    // 3) flash attention (fp16 1+1-term, exp2, no-max)
    flash_kernel<<<dim3(T_SEQ / 64, HEADS), 128>>>();

    // 4) output projection (3-term bf16) -> out
    gemm_mma_kernel<1><<<dim3(T_SEQ / 128, DIM / 64), 256>>>(yh, yl, wph, wpl, out);
}

// round 10
// speedup vs baseline: 1.9050x; 1.0129x over previous
#include <cuda_runtime.h>
#include <cuda_bf16.h>
#include <cuda_fp16.h>
#include <float.h>
#include <stdint.h>

typedef __nv_bfloat16 bf16;
typedef __half fp16;

#define T_SEQ   4096
#define DIM     768
#define HEADS   12
#define HEAD_D  64
#define N_QKV   (3 * DIM)
#define RMS_EPS 1.1920928955078125e-07f
// q pre-scale: 0.12 * log2(e)  (softmax computed with exp2)
#define Q_SCALE 0.17312340490667562f
#define CHUNK   16            // key tiles (of 64) per flash block

// ---------------- scratch ----------------------------------------------------
__device__ float g_qkv[2 * HEADS * T_SEQ * HEAD_D];   // f32 q,k head-major
__device__ fp16  g_q [HEADS * T_SEQ * HEAD_D];
__device__ fp16  g_k [HEADS * T_SEQ * HEAD_D];
__device__ fp16  g_v [HEADS * T_SEQ * HEAD_D];
__device__ float g_oacc[HEADS * T_SEQ * HEAD_D];      // split-K partial O
__device__ float g_lacc[HEADS * T_SEQ];               // split-K partial l
__device__ bf16  g_xh[T_SEQ * DIM],  g_xl[T_SEQ * DIM];
__device__ bf16  g_wqh[N_QKV * DIM], g_wql[N_QKV * DIM];
__device__ bf16  g_wph[DIM * DIM],   g_wpl[DIM * DIM];
__device__ bf16  g_yh[T_SEQ * DIM],  g_yl[T_SEQ * DIM];

// ---------------- helpers ----------------------------------------------------
__device__ __forceinline__ uint32_t smem_u32(const void* p) {
    return (uint32_t)__cvta_generic_to_shared(p);
}
__device__ __forceinline__ void ldsm_x4(uint32_t& r0, uint32_t& r1,
                                        uint32_t& r2, uint32_t& r3, uint32_t a) {
    asm volatile("ldmatrix.sync.aligned.m8n8.x4.shared.b16 {%0,%1,%2,%3},[%4];\n"
                 : "=r"(r0), "=r"(r1), "=r"(r2), "=r"(r3) : "r"(a));
}
__device__ __forceinline__ void ldsm_x4_t(uint32_t& r0, uint32_t& r1,
                                          uint32_t& r2, uint32_t& r3, uint32_t a) {
    asm volatile("ldmatrix.sync.aligned.m8n8.x4.trans.shared.b16 {%0,%1,%2,%3},[%4];\n"
                 : "=r"(r0), "=r"(r1), "=r"(r2), "=r"(r3) : "r"(a));
}
__device__ __forceinline__ void mma_bf(float* d, const uint32_t* a, const uint32_t* b) {
    asm volatile(
        "mma.sync.aligned.m16n8k16.row.col.f32.bf16.bf16.f32 "
        "{%0,%1,%2,%3},{%4,%5,%6,%7},{%8,%9},{%0,%1,%2,%3};\n"
        : "+f"(d[0]), "+f"(d[1]), "+f"(d[2]), "+f"(d[3])
        : "r"(a[0]), "r"(a[1]), "r"(a[2]), "r"(a[3]), "r"(b[0]), "r"(b[1]));
}
__device__ __forceinline__ void mma_fp(float* d, const uint32_t* a, const uint32_t* b) {
    asm volatile(
        "mma.sync.aligned.m16n8k16.row.col.f32.f16.f16.f32 "
        "{%0,%1,%2,%3},{%4,%5,%6,%7},{%8,%9},{%0,%1,%2,%3};\n"
        : "+f"(d[0]), "+f"(d[1]), "+f"(d[2]), "+f"(d[3])
        : "r"(a[0]), "r"(a[1]), "r"(a[2]), "r"(a[3]), "r"(b[0]), "r"(b[1]));
}
__device__ __forceinline__ uint32_t pack_bf2(float x, float y) {
    __nv_bfloat162 t = __floats2bfloat162_rn(x, y);
    return *(uint32_t*)&t;
}
__device__ __forceinline__ uint32_t pack_h2(float x, float y) {
    __half2 t = __floats2half2_rn(x, y);
    return *(uint32_t*)&t;
}
__device__ __forceinline__ void split_bf(float v, bf16& h, bf16& l) {
    h = __float2bfloat16(v);
    l = __float2bfloat16(v - __bfloat162float(h));
}

// One kernel splits x, qkv_w, c_proj_w AND zeroes the split-K accumulators
#define N_X  (T_SEQ * DIM)
#define N_WQ (N_QKV * DIM)
#define N_WP (DIM * DIM)
#define N_OA (HEADS * T_SEQ * HEAD_D)
#define N_LA (HEADS * T_SEQ)
__global__ void prep_kernel(const float* __restrict__ x,
                            const float* __restrict__ wq,
                            const float* __restrict__ wp) {
    int i = blockIdx.x * blockDim.x + threadIdx.x;
    if (i < N_X) {
        bf16 h, l; split_bf(x[i], h, l); g_xh[i] = h; g_xl[i] = l;
    } else if (i < N_X + N_WQ) {
        int j = i - N_X;
        bf16 h, l; split_bf(wq[j], h, l); g_wqh[j] = h; g_wql[j] = l;
    } else if (i < N_X + N_WQ + N_WP) {
        int j = i - N_X - N_WQ;
        bf16 h, l; split_bf(wp[j], h, l); g_wph[j] = h; g_wpl[j] = l;
    } else if (i < N_X + N_WQ + N_WP + N_OA) {
        g_oacc[i - N_X - N_WQ - N_WP] = 0.f;
    } else if (i < N_X + N_WQ + N_WP + N_OA + N_LA) {
        g_lacc[i - N_X - N_WQ - N_WP - N_OA] = 0.f;
    }
}

// ---------------- GEMM: C = A @ B^T, 3-term bf16 (128x64 tile, BK=32) --------
// MODE 0: QKV — q,k -> f32 g_qkv head-major; v -> fp16 g_v direct
// MODE 1: proj — plain f32 write to C
#define LDA 40
template<int MODE>
__global__ __launch_bounds__(256) void gemm_mma_kernel(
    const bf16* __restrict__ Ah, const bf16* __restrict__ Al,
    const bf16* __restrict__ Bh, const bf16* __restrict__ Bl,
    float* __restrict__ C)
{
    constexpr int K = 768;
    __shared__ bf16 sA[2][128][LDA];
    __shared__ bf16 sB[2][64][LDA];
    const int tid = threadIdx.x;
    const int wid = tid >> 5, lane = tid & 31;
    const int wm = wid & 3, wn = wid >> 2;
    const int m0 = blockIdx.x * 128, n0 = blockIdx.y * 64;
    const int g = lane >> 2, q = lane & 3;

    float acc[2][4][4];
    #pragma unroll
    for (int a = 0; a < 2; a++)
        #pragma unroll
        for (int b = 0; b < 4; b++)
            #pragma unroll
            for (int c = 0; c < 4; c++) acc[a][b][c] = 0.f;

    for (int k0 = 0; k0 < K; k0 += 32) {
        __syncthreads();
        #pragma unroll
        for (int i = 0; i < 2; i++) {
            int c = tid + i * 256;
            int r = c >> 2, col = (c & 3) * 8;
            size_t go = (size_t)(m0 + r) * K + k0 + col;
            *(uint4*)&sA[0][r][col] = *(const uint4*)(Ah + go);
            *(uint4*)&sA[1][r][col] = *(const uint4*)(Al + go);
        }
        {
            int r = tid >> 2, col = (tid & 3) * 8;
            size_t go = (size_t)(n0 + r) * K + k0 + col;
            *(uint4*)&sB[0][r][col] = *(const uint4*)(Bh + go);
            *(uint4*)&sB[1][r][col] = *(const uint4*)(Bl + go);
        }
        __syncthreads();

        uint32_t aF[2][2][2][4];
        uint32_t bF[2][4][2][2];
        #pragma unroll
        for (int v = 0; v < 2; v++) {
            #pragma unroll
            for (int mt = 0; mt < 2; mt++)
                #pragma unroll
                for (int kt = 0; kt < 2; kt++) {
                    uint32_t ad = smem_u32(&sA[v][wm * 32 + mt * 16 + (lane & 15)]
                                              [kt * 16 + (lane >> 4) * 8]);
                    ldsm_x4(aF[v][mt][kt][0], aF[v][mt][kt][1],
                            aF[v][mt][kt][2], aF[v][mt][kt][3], ad);
                }
            #pragma unroll
            for (int np = 0; np < 2; np++)
                #pragma unroll
                for (int kt = 0; kt < 2; kt++) {
                    uint32_t ad = smem_u32(&sB[v][wn * 32 + np * 16 + (lane & 15)]
                                              [kt * 16 + (lane >> 4) * 8]);
                    uint32_t r0, r1, r2, r3;
                    ldsm_x4(r0, r1, r2, r3, ad);
                    bF[v][np * 2 + 0][kt][0] = r0; bF[v][np * 2 + 1][kt][0] = r1;
                    bF[v][np * 2 + 0][kt][1] = r2; bF[v][np * 2 + 1][kt][1] = r3;
                }
        }
        #pragma unroll
        for (int mt = 0; mt < 2; mt++)
            #pragma unroll
            for (int nt = 0; nt < 4; nt++)
                #pragma unroll
                for (int kt = 0; kt < 2; kt++) {
                    mma_bf(acc[mt][nt], aF[0][mt][kt], bF[0][nt][kt]);
                    mma_bf(acc[mt][nt], aF[0][mt][kt], bF[1][nt][kt]);
                    mma_bf(acc[mt][nt], aF[1][mt][kt], bF[0][nt][kt]);
                }
    }

    #pragma unroll
    for (int mt = 0; mt < 2; mt++)
        #pragma unroll
        for (int nt = 0; nt < 4; nt++) {
            int r0 = m0 + wm * 32 + mt * 16 + g;
            int cc = n0 + wn * 32 + nt * 8 + q * 2;
            float* a = acc[mt][nt];
            if (MODE == 0) {
                int blk = cc >> 6;
                if (blk < 24) {
                    size_t base = (size_t)blk * (T_SEQ * HEAD_D) + (cc & 63);
                    *(float2*)&g_qkv[base + (size_t)r0 * HEAD_D]       = make_float2(a[0], a[1]);
                    *(float2*)&g_qkv[base + (size_t)(r0 + 8) * HEAD_D] = make_float2(a[2], a[3]);
                } else {
                    size_t base = (size_t)(blk - 24) * (T_SEQ * HEAD_D) + (cc & 63);
                    *(uint32_t*)&g_v[base + (size_t)r0 * HEAD_D]       = pack_h2(a[0], a[1]);
                    *(uint32_t*)&g_v[base + (size_t)(r0 + 8) * HEAD_D] = pack_h2(a[2], a[3]);
                }
            } else {
                *(float2*)&C[(size_t)r0 * DIM + cc]       = make_float2(a[0], a[1]);
                *(float2*)&C[(size_t)(r0 + 8) * DIM + cc] = make_float2(a[2], a[3]);
            }
        }
}

// ---------------- RMSNorm + rotary -> fp16 q (scaled) / k --------------------
__global__ void rms_rope_kernel() {
    const int t = blockIdx.x;
    const int comp = blockIdx.y;
    const int h = threadIdx.x >> 5;
    const int lane = threadIdx.x & 31;
    const size_t hoff = (size_t)h * (T_SEQ * HEAD_D) + (size_t)t * HEAD_D;
    const float* p = g_qkv + (size_t)comp * HEADS * T_SEQ * HEAD_D + hoff;
    float v0 = p[lane], v1 = p[lane + 32];

    float ss = v0 * v0 + v1 * v1;
    #pragma unroll
    for (int o = 16; o >= 1; o >>= 1) ss += __shfl_xor_sync(0xffffffffu, ss, o);
    float r = rsqrtf(ss * (1.0f / HEAD_D) + RMS_EPS);
    v0 *= r; v1 *= r;
    if (lane < 16) {
        float fr = exp2f(-10.0f * (float)lane / 15.0f);
        float th = (float)t * fr, s, c;
        sincosf(th, &s, &c);
        float y0 =  v0 * c + v1 * s;
        float y1 = -v0 * s + v1 * c;
        v0 = y0; v1 = y1;
    }
    if (comp == 0) {
        v0 *= Q_SCALE; v1 *= Q_SCALE;
        g_q[hoff + lane]      = __float2half_rn(v0);
        g_q[hoff + lane + 32] = __float2half_rn(v1);
    } else {
        g_k[hoff + lane]      = __float2half_rn(v0);
        g_k[hoff + lane + 32] = __float2half_rn(v1);
    }
}

// ---------------- Flash split-K chunk: fp16 1+1-term, exp2, no-max -----------
// grid (64, HEADS, 4): z = key chunk. Partial O,l accumulate exactly (no max).
#define FLD 72
__global__ __launch_bounds__(128) void flash_kernel() {
    const int qb = (int)(gridDim.x - 1) - (int)blockIdx.x;   // heavy first
    const int ch = blockIdx.z;
    const int kb_lo = ch * CHUNK;
    if (kb_lo > qb) return;
    const int kb_hi = min(qb, kb_lo + CHUNK - 1);
    const int h = blockIdx.y;
    const int tid = threadIdx.x, wid = tid >> 5, lane = tid & 31;
    const int g = lane >> 2, q = lane & 3;

    __shared__ fp16 sK[64][FLD];
    __shared__ fp16 sV[64][FLD];

    const size_t HS = (size_t)T_SEQ * HEAD_D;
    const fp16* Q  = g_q + (size_t)h * HS;
    const fp16* Kk = g_k + (size_t)h * HS;
    const fp16* Vv = g_v + (size_t)h * HS;

    uint32_t qF[4][4];
    {
        int r0 = qb * 64 + wid * 16 + g;
        #pragma unroll
        for (int kt = 0; kt < 4; kt++) {
            int c = kt * 16 + q * 2;
            qF[kt][0] = *(const uint32_t*)(Q + (size_t)r0 * HEAD_D + c);
            qF[kt][1] = *(const uint32_t*)(Q + (size_t)(r0 + 8) * HEAD_D + c);
            qF[kt][2] = *(const uint32_t*)(Q + (size_t)r0 * HEAD_D + c + 8);
            qF[kt][3] = *(const uint32_t*)(Q + (size_t)(r0 + 8) * HEAD_D + c + 8);
        }
    }

    float o[8][4];
    #pragma unroll
    for (int i = 0; i < 8; i++)
        #pragma unroll
        for (int j = 0; j < 4; j++) o[i][j] = 0.f;
    float l0_ = 0.f, l1_ = 0.f;

    for (int kb = kb_lo; kb <= kb_hi; kb++) {
        __syncthreads();
        #pragma unroll
        for (int i = 0; i < 4; i++) {
            int c = tid + i * 128;
            int r = c >> 3, col = (c & 7) * 8;
            size_t go = (size_t)(kb * 64 + r) * HEAD_D + col;
            *(uint4*)&sK[r][col] = *(const uint4*)(Kk + go);
            *(uint4*)&sV[r][col] = *(const uint4*)(Vv + go);
        }
        __syncthreads();

        // ---- S = Q K^T ----
        float s[8][4];
        #pragma unroll
        for (int i = 0; i < 8; i++)
            #pragma unroll
            for (int j = 0; j < 4; j++) s[i][j] = 0.f;

        #pragma unroll
        for (int kt = 0; kt < 4; kt++) {
            uint32_t bh[8][2];
            #pragma unroll
            for (int np = 0; np < 4; np++) {
                uint32_t ad = smem_u32(&sK[np * 16 + (lane & 15)]
                                          [kt * 16 + (lane >> 4) * 8]);
                uint32_t r0, r1, r2, r3;
                ldsm_x4(r0, r1, r2, r3, ad);
                bh[np * 2][0] = r0; bh[np * 2 + 1][0] = r1;
                bh[np * 2][1] = r2; bh[np * 2 + 1][1] = r3;
            }
            #pragma unroll
            for (int nt = 0; nt < 8; nt++)
                mma_fp(s[nt], qF[kt], bh[nt]);
        }

        // ---- causal mask on diagonal tile ----
        if (kb == qb) {
            int rl0 = wid * 16 + g, rl1 = rl0 + 8;
            #pragma unroll
            for (int nt = 0; nt < 8; nt++) {
                int c0 = nt * 8 + q * 2, c1 = c0 + 1;
                if (c0 > rl0) s[nt][0] = -1e30f;
                if (c1 > rl0) s[nt][1] = -1e30f;
                if (c0 > rl1) s[nt][2] = -1e30f;
                if (c1 > rl1) s[nt][3] = -1e30f;
            }
        }

        // ---- P = exp2(S) + row sums ----
        float rs0 = 0.f, rs1 = 0.f;
        #pragma unroll
        for (int nt = 0; nt < 8; nt++) {
            s[nt][0] = exp2f(s[nt][0]);
            s[nt][1] = exp2f(s[nt][1]);
            s[nt][2] = exp2f(s[nt][2]);
            s[nt][3] = exp2f(s[nt][3]);
            rs0 += s[nt][0] + s[nt][1];
            rs1 += s[nt][2] + s[nt][3];
        }
        rs0 += __shfl_xor_sync(0xffffffffu, rs0, 1);
        rs0 += __shfl_xor_sync(0xffffffffu, rs0, 2);
        rs1 += __shfl_xor_sync(0xffffffffu, rs1, 1);
        rs1 += __shfl_xor_sync(0xffffffffu, rs1, 2);
        l0_ += rs0;
        l1_ += rs1;

        // ---- P -> fp16 fragments ----
        uint32_t pF[4][4];
        #pragma unroll
        for (int kt = 0; kt < 4; kt++) {
            #pragma unroll
            for (int half = 0; half < 2; half++) {
                float* sv = s[2 * kt + half];
                pF[kt][0 + 2 * half] = pack_h2(sv[0], sv[1]);
                pF[kt][1 + 2 * half] = pack_h2(sv[2], sv[3]);
            }
        }

        // ---- O += P V ----
        #pragma unroll
        for (int kt = 0; kt < 4; kt++) {
            uint32_t bv[8][2];
            #pragma unroll
            for (int np = 0; np < 4; np++) {
                uint32_t ad = smem_u32(&sV[kt * 16 + (lane & 15)]
                                          [np * 16 + (lane >> 4) * 8]);
                uint32_t r0, r1, r2, r3;
                ldsm_x4_t(r0, r1, r2, r3, ad);
                bv[np * 2][0] = r0; bv[np * 2][1] = r1;
                bv[np * 2 + 1][0] = r2; bv[np * 2 + 1][1] = r3;
            }
            #pragma unroll
            for (int nt = 0; nt < 8; nt++)
                mma_fp(o[nt], pF[kt], bv[nt]);
        }
    }

    // ---- accumulate partials ----
    int r0 = qb * 64 + wid * 16 + g;
    float* Oa = g_oacc + (size_t)h * HS;
    #pragma unroll
    for (int nt = 0; nt < 8; nt++) {
        int d = nt * 8 + q * 2;
        atomicAdd(&Oa[(size_t)r0 * HEAD_D + d],           o[nt][0]);
        atomicAdd(&Oa[(size_t)r0 * HEAD_D + d + 1],       o[nt][1]);
        atomicAdd(&Oa[(size_t)(r0 + 8) * HEAD_D + d],     o[nt][2]);
        atomicAdd(&Oa[(size_t)(r0 + 8) * HEAD_D + d + 1], o[nt][3]);
    }
    if (q == 0) {
        atomicAdd(&g_lacc[(size_t)h * T_SEQ + r0],     l0_);
        atomicAdd(&g_lacc[(size_t)h * T_SEQ + r0 + 8], l1_);
    }
}

// ---------------- normalize + bf16 split -> y hi/lo --------------------------
__global__ void norm_split_kernel() {
    const int t = blockIdx.x;
    const int tid = threadIdx.x;       // 0..767
    const int h = tid >> 6, d = tid & 63;
    float l = g_lacc[(size_t)h * T_SEQ + t];
    float o = g_oacc[((size_t)h * T_SEQ + t) * HEAD_D + d];
    float y = o / l;
    bf16 hi, lo; split_bf(y, hi, lo);
    g_yh[(size_t)t * DIM + tid] = hi;
    g_yl[(size_t)t * DIM + tid] = lo;
}

// ---------------------------------------------------------------------------
extern "C" void kernel_launch(void* const* d_in, const int* in_sizes, int n_in,
                              void* d_out, int out_size)
{
    const float* x        = (const float*)d_in[0];
    const float* qkv_w    = (const float*)d_in[1];
    const float* c_proj_w = (const float*)d_in[2];
    float* out            = (float*)d_out;

    bf16 *xh, *xl, *wqh, *wql, *wph, *wpl, *yh, *yl;
    cudaGetSymbolAddress((void**)&xh,  g_xh);  cudaGetSymbolAddress((void**)&xl,  g_xl);
    cudaGetSymbolAddress((void**)&wqh, g_wqh); cudaGetSymbolAddress((void**)&wql, g_wql);
    cudaGetSymbolAddress((void**)&wph, g_wph); cudaGetSymbolAddress((void**)&wpl, g_wpl);
    cudaGetSymbolAddress((void**)&yh,  g_yh);  cudaGetSymbolAddress((void**)&yl,  g_yl);

    // 0) fused split + accumulator zero
    {
        int n = N_X + N_WQ + N_WP + N_OA + N_LA;
        prep_kernel<<<(n + 255) / 256, 256>>>(x, qkv_w, c_proj_w);
    }

    // 1) QKV projection (3-term bf16) -> f32 q,k + fp16 v
    gemm_mma_kernel<0><<<dim3(T_SEQ / 128, N_QKV / 64), 256>>>(
        xh, xl, wqh, wql, nullptr);

    // 2) rms + rope -> fp16 q (×0.12·log2e), k
    rms_rope_kernel<<<dim3(T_SEQ, 2), HEADS * 32>>>();

    // 3) flash attention, split-K over 4 key chunks
    flash_kernel<<<dim3(T_SEQ / 64, HEADS, 4), 128>>>();

    // 4) normalize + split y
    norm_split_kernel<<<T_SEQ, DIM>>>();

    // 5) output projection (3-term bf16) -> out
    gemm_mma_kernel<1><<<dim3(T_SEQ / 128, DIM / 64), 256>>>(yh, yl, wph, wpl, out);
}